// round 2
// baseline (speedup 1.0000x reference)
#include <cuda_runtime.h>
#include <math.h>

// Problem dims (fixed by setup_inputs)
#define T_TOK 8192      // B*S tokens
#define D_DIM 2048
#define E_EXP 8
#define H_DIM 2048
#define C_CAP 2048      // capacity = k*T/E
#define B_BATCH 4
#define S_SEQ 2048

// ---------------- device scratch (allocation-free) ----------------
__device__ int   g_e0[T_TOK], g_e1[T_TOK];
__device__ float g_g0[T_TOK], g_g1[T_TOK];
__device__ int   g_p0[T_TOK], g_p1[T_TOK];      // position in expert buffer, -1 if dropped
__device__ int   g_src[E_EXP * C_CAP];          // token id filling slot (e,c), -1 empty
__device__ float g_w2sum[E_EXP * H_DIM];        // sum_d W2[e,h,d]
__device__ float g_b2sum[E_EXP];                // sum_d b2[e,d]
__device__ float g_rowsum[E_EXP * C_CAP];       // sum_h relu(z)*w2sum
__device__ float g_y[T_TOK];

// ---------------- K0: per-launch reset (graph replays must be deterministic) ----------------
__global__ void k_init() {
    int i = blockIdx.x * blockDim.x + threadIdx.x;
    if (i < E_EXP * C_CAP) {
        g_src[i] = -1;
        g_rowsum[i] = 0.f;
    }
}

// ---------------- K1: gating (logits + top2 + normalized gates) ----------------
// one warp per token; 8 warps / block
__global__ void k_gate(const float* __restrict__ x, const float* __restrict__ Wg) {
    int warp = threadIdx.x >> 5;
    int lane = threadIdx.x & 31;
    int tok = blockIdx.x * 8 + warp;
    if (tok >= T_TOK) return;
    const float* xr = x + (size_t)tok * D_DIM;

    float acc[8];
#pragma unroll
    for (int e = 0; e < 8; e++) acc[e] = 0.f;

    for (int k = lane; k < D_DIM; k += 32) {
        float xv = xr[k];
        const float* wr = Wg + (size_t)k * 8;
        float4 w0 = *(const float4*)(wr);
        float4 w1 = *(const float4*)(wr + 4);
        acc[0] = fmaf(xv, w0.x, acc[0]);
        acc[1] = fmaf(xv, w0.y, acc[1]);
        acc[2] = fmaf(xv, w0.z, acc[2]);
        acc[3] = fmaf(xv, w0.w, acc[3]);
        acc[4] = fmaf(xv, w1.x, acc[4]);
        acc[5] = fmaf(xv, w1.y, acc[5]);
        acc[6] = fmaf(xv, w1.z, acc[6]);
        acc[7] = fmaf(xv, w1.w, acc[7]);
    }
#pragma unroll
    for (int e = 0; e < 8; e++) {
#pragma unroll
        for (int off = 16; off > 0; off >>= 1)
            acc[e] += __shfl_xor_sync(0xffffffffu, acc[e], off);
    }
    if (lane == 0) {
        // top-1: strict > keeps lowest index on ties (matches lax.top_k)
        float l0 = acc[0]; int i0 = 0;
#pragma unroll
        for (int e = 1; e < 8; e++) if (acc[e] > l0) { l0 = acc[e]; i0 = e; }
        float l1 = -INFINITY; int i1 = 0;
#pragma unroll
        for (int e = 0; e < 8; e++) if (e != i0 && acc[e] > l1) { l1 = acc[e]; i1 = e; }
        // normalized top-2 gates = 2-way softmax of top-2 logits
        float g0 = 1.f / (1.f + __expf(l1 - l0));  // l1 <= l0, stable
        g_e0[tok] = i0; g_e1[tok] = i1;
        g_g0[tok] = g0; g_g1[tok] = 1.f - g0;
    }
}

// ---------------- K2: dispatch scan (single block) ----------------
// Order: all choice-0 assignments in token order, then all choice-1 (GShard k-major).
#define SCAN_T 512
#define TOK_PER_T (T_TOK / SCAN_T)   // 16
__global__ void k_scan() {
    __shared__ int shCnt[SCAN_T * 8];
    __shared__ int shScan[SCAN_T * 8];
    __shared__ int shTot[8];
    int t = threadIdx.x;

    // -------- choice 0 --------
    for (int e = 0; e < 8; e++) shCnt[t * 8 + e] = 0;
    for (int i = 0; i < TOK_PER_T; i++) {
        int tok = t * TOK_PER_T + i;
        shCnt[t * 8 + g_e0[tok]]++;
    }
    for (int e = 0; e < 8; e++) shScan[t * 8 + e] = shCnt[t * 8 + e];
    __syncthreads();
    // inclusive Hillis-Steele scan over 512 rows of int8-vectors
    for (int s = 1; s < SCAN_T; s <<= 1) {
        int v[8];
        if (t >= s) {
            for (int e = 0; e < 8; e++) v[e] = shScan[(t - s) * 8 + e];
        }
        __syncthreads();
        if (t >= s) {
            for (int e = 0; e < 8; e++) shScan[t * 8 + e] += v[e];
        }
        __syncthreads();
    }
    if (t == 0) {
        for (int e = 0; e < 8; e++) shTot[e] = shScan[(SCAN_T - 1) * 8 + e];
    }
    // exclusive offset -> running counter in shCnt
    for (int e = 0; e < 8; e++) shCnt[t * 8 + e] = shScan[t * 8 + e] - shCnt[t * 8 + e];
    __syncthreads();
    for (int i = 0; i < TOK_PER_T; i++) {
        int tok = t * TOK_PER_T + i;
        int e = g_e0[tok];
        int pos = shCnt[t * 8 + e]++;   // count ALL prior assignments (incl. overflow)
        if (pos < C_CAP) { g_p0[tok] = pos; g_src[e * C_CAP + pos] = tok; }
        else             { g_p0[tok] = -1; }
    }
    __syncthreads();

    // -------- choice 1 (base = total choice-0 counts) --------
    for (int e = 0; e < 8; e++) shCnt[t * 8 + e] = 0;
    for (int i = 0; i < TOK_PER_T; i++) {
        int tok = t * TOK_PER_T + i;
        shCnt[t * 8 + g_e1[tok]]++;
    }
    for (int e = 0; e < 8; e++) shScan[t * 8 + e] = shCnt[t * 8 + e];
    __syncthreads();
    for (int s = 1; s < SCAN_T; s <<= 1) {
        int v[8];
        if (t >= s) {
            for (int e = 0; e < 8; e++) v[e] = shScan[(t - s) * 8 + e];
        }
        __syncthreads();
        if (t >= s) {
            for (int e = 0; e < 8; e++) shScan[t * 8 + e] += v[e];
        }
        __syncthreads();
    }
    for (int e = 0; e < 8; e++)
        shCnt[t * 8 + e] = shScan[t * 8 + e] - shCnt[t * 8 + e] + shTot[e];
    __syncthreads();
    for (int i = 0; i < TOK_PER_T; i++) {
        int tok = t * TOK_PER_T + i;
        int e = g_e1[tok];
        int pos = shCnt[t * 8 + e]++;
        if (pos < C_CAP) { g_p1[tok] = pos; g_src[e * C_CAP + pos] = tok; }
        else             { g_p1[tok] = -1; }
    }
}

// ---------------- K3a: w2sum[e,h] = sum_d W2[e,h,d] ----------------
__global__ void k_w2sum(const float* __restrict__ W2) {
    int gw = (blockIdx.x * blockDim.x + threadIdx.x) >> 5;
    int lane = threadIdx.x & 31;
    if (gw >= E_EXP * H_DIM) return;
    const float* r = W2 + (size_t)gw * D_DIM;
    float s = 0.f;
    for (int k = lane * 4; k < D_DIM; k += 128) {
        float4 v = *(const float4*)(r + k);
        s += (v.x + v.y) + (v.z + v.w);
    }
#pragma unroll
    for (int off = 16; off > 0; off >>= 1) s += __shfl_xor_sync(0xffffffffu, s, off);
    if (lane == 0) g_w2sum[gw] = s;
}

// ---------------- K3b: b2sum[e] = sum_d b2[e,d] ----------------
__global__ void k_b2sum(const float* __restrict__ b2) {
    int w = threadIdx.x >> 5, lane = threadIdx.x & 31;
    if (w >= E_EXP) return;
    float s = 0.f;
    for (int k = lane; k < D_DIM; k += 32) s += b2[(size_t)w * D_DIM + k];
#pragma unroll
    for (int off = 16; off > 0; off >>= 1) s += __shfl_xor_sync(0xffffffffu, s, off);
    if (lane == 0) g_b2sum[w] = s;
}

// ---------------- K4: fused expert GEMM + relu + w2sum reduction ----------------
// z[c,h] = sum_d x[src[e,c],d] * W1[e,d,h] + b1[e,h]
// rowsum[e,c] += sum_h relu(z[c,h]) * w2sum[e,h]   (atomicAdd over H tiles)
#define BM 128
#define BN 128
#define BK 8
__global__ void __launch_bounds__(256) k_ffn(const float* __restrict__ x,
                                             const float* __restrict__ W1,
                                             const float* __restrict__ b1) {
    __shared__ float As[2][BK][BM];   // transposed A tile
    __shared__ float Bs[2][BK][BN];
    __shared__ int   sSrc[BM];
    __shared__ float sW2[BN];
    __shared__ float sB1[BN];

    const int e    = blockIdx.z;
    const int row0 = blockIdx.y * BM;
    const int col0 = blockIdx.x * BN;
    const int tid  = threadIdx.x;

    if (tid < BM) sSrc[tid] = g_src[e * C_CAP + row0 + tid];
    if (tid < BN) {
        sW2[tid] = g_w2sum[(size_t)e * H_DIM + col0 + tid];
        sB1[tid] = b1[(size_t)e * H_DIM + col0 + tid];
    }
    __syncthreads();

    // loaders
    const int ar = tid >> 1;            // A row within tile 0..127
    const int ak = (tid & 1) * 4;       // A k offset 0 or 4
    const int bk = tid >> 5;            // B k row 0..7
    const int bc = (tid & 31) * 4;      // B col 0..124

    const int srcTok = sSrc[ar];
    const float* Aptr = x + (size_t)(srcTok >= 0 ? srcTok : 0) * D_DIM + ak;
    const float* Wbase = W1 + (size_t)e * D_DIM * H_DIM + col0;

    float4 aReg, bReg;
    const float4 zero4 = make_float4(0.f, 0.f, 0.f, 0.f);

    // preload tile 0
    aReg = (srcTok >= 0) ? *(const float4*)(Aptr) : zero4;
    bReg = *(const float4*)(Wbase + (size_t)bk * H_DIM + bc);
    As[0][ak + 0][ar] = aReg.x; As[0][ak + 1][ar] = aReg.y;
    As[0][ak + 2][ar] = aReg.z; As[0][ak + 3][ar] = aReg.w;
    *(float4*)&Bs[0][bk][bc] = bReg;
    __syncthreads();

    const int tx = tid & 15;   // col group: cols tx*8..+7
    const int ty = tid >> 4;   // row group: rows ty*8..+7

    float acc[8][8];
#pragma unroll
    for (int i = 0; i < 8; i++)
#pragma unroll
        for (int j = 0; j < 8; j++) acc[i][j] = 0.f;

    const int NK = D_DIM / BK;  // 256
    for (int kt = 0; kt < NK; kt++) {
        const int buf = kt & 1;
        if (kt + 1 < NK) {
            const int kbase = (kt + 1) * BK;
            aReg = (srcTok >= 0) ? *(const float4*)(Aptr + kbase) : zero4;
            bReg = *(const float4*)(Wbase + (size_t)(kbase + bk) * H_DIM + bc);
        }
#pragma unroll
        for (int kk = 0; kk < BK; kk++) {
            float a[8], b[8];
            *(float4*)(a)     = *(const float4*)&As[buf][kk][ty * 8];
            *(float4*)(a + 4) = *(const float4*)&As[buf][kk][ty * 8 + 4];
            *(float4*)(b)     = *(const float4*)&Bs[buf][kk][tx * 8];
            *(float4*)(b + 4) = *(const float4*)&Bs[buf][kk][tx * 8 + 4];
#pragma unroll
            for (int i = 0; i < 8; i++)
#pragma unroll
                for (int j = 0; j < 8; j++)
                    acc[i][j] = fmaf(a[i], b[j], acc[i][j]);
        }
        if (kt + 1 < NK) {
            const int nb = buf ^ 1;
            As[nb][ak + 0][ar] = aReg.x; As[nb][ak + 1][ar] = aReg.y;
            As[nb][ak + 2][ar] = aReg.z; As[nb][ak + 3][ar] = aReg.w;
            *(float4*)&Bs[nb][bk][bc] = bReg;
        }
        __syncthreads();
    }

    // epilogue: relu + dot with w2sum, reduce across the 16 col-group threads
    float w2f[8], b1f[8];
    *(float4*)(w2f)     = *(const float4*)&sW2[tx * 8];
    *(float4*)(w2f + 4) = *(const float4*)&sW2[tx * 8 + 4];
    *(float4*)(b1f)     = *(const float4*)&sB1[tx * 8];
    *(float4*)(b1f + 4) = *(const float4*)&sB1[tx * 8 + 4];

    float rp[8];
#pragma unroll
    for (int i = 0; i < 8; i++) {
        float s = 0.f;
#pragma unroll
        for (int j = 0; j < 8; j++) {
            float v = acc[i][j] + b1f[j];
            v = fmaxf(v, 0.f);
            s = fmaf(v, w2f[j], s);
        }
        rp[i] = s;
    }
    // partners share ty (same 16-lane half of the warp): xor over low 4 lane bits
#pragma unroll
    for (int off = 8; off > 0; off >>= 1)
#pragma unroll
        for (int i = 0; i < 8; i++)
            rp[i] += __shfl_xor_sync(0xffffffffu, rp[i], off);

    if (tx == 0) {
#pragma unroll
        for (int i = 0; i < 8; i++)
            atomicAdd(&g_rowsum[e * C_CAP + row0 + ty * 8 + i], rp[i]);
    }
}

// ---------------- K5: combine ----------------
__global__ void k_combine() {
    int t = blockIdx.x * blockDim.x + threadIdx.x;
    if (t >= T_TOK) return;
    float y = 0.f;
    int p0 = g_p0[t];
    if (p0 >= 0) {
        int e = g_e0[t];
        y += g_g0[t] * (g_rowsum[e * C_CAP + p0] + g_b2sum[e]);
    }
    int p1 = g_p1[t];
    if (p1 >= 0) {
        int e = g_e1[t];
        y += g_g1[t] * (g_rowsum[e * C_CAP + p1] + g_b2sum[e]);
    }
    g_y[t] = y;
}

// ---------------- K6: log_softmax over S per batch ----------------
__global__ void k_lsm(float* __restrict__ out) {
    __shared__ float red[256];
    int b = blockIdx.x, tid = threadIdx.x;
    const float* yr = g_y + (size_t)b * S_SEQ;

    float m = -INFINITY;
    for (int s = tid; s < S_SEQ; s += 256) m = fmaxf(m, yr[s]);
    red[tid] = m; __syncthreads();
    for (int off = 128; off > 0; off >>= 1) {
        if (tid < off) red[tid] = fmaxf(red[tid], red[tid + off]);
        __syncthreads();
    }
    m = red[0]; __syncthreads();

    float sum = 0.f;
    for (int s = tid; s < S_SEQ; s += 256) sum += expf(yr[s] - m);
    red[tid] = sum; __syncthreads();
    for (int off = 128; off > 0; off >>= 1) {
        if (tid < off) red[tid] += red[tid + off];
        __syncthreads();
    }
    float lse = m + logf(red[0]);

    for (int s = tid; s < S_SEQ; s += 256)
        out[(size_t)b * S_SEQ + s] = yr[s] - lse;
}

// ---------------- launch ----------------
extern "C" void kernel_launch(void* const* d_in, const int* in_sizes, int n_in,
                              void* d_out, int out_size) {
    const float* x  = (const float*)d_in[0];
    const float* Wg = (const float*)d_in[1];
    const float* W1 = (const float*)d_in[2];
    const float* b1 = (const float*)d_in[3];
    const float* W2 = (const float*)d_in[4];
    const float* b2 = (const float*)d_in[5];
    float* out = (float*)d_out;

    k_init<<<(E_EXP * C_CAP + 255) / 256, 256>>>();
    k_gate<<<T_TOK / 8, 256>>>(x, Wg);
    k_scan<<<1, SCAN_T>>>();
    k_w2sum<<<(E_EXP * H_DIM) / 8, 256>>>(W2);
    k_b2sum<<<1, 256>>>(b2);
    k_ffn<<<dim3(H_DIM / BN, C_CAP / BM, E_EXP), 256>>>(x, W1, b1);
    k_combine<<<T_TOK / 256, 256>>>();
    k_lsm<<<B_BATCH, 256>>>(out);
}

// round 4
// speedup vs baseline: 1.6501x; 1.6501x over previous
#include <cuda_runtime.h>
#include <cuda_bf16.h>
#include <math.h>
#include <stdint.h>

// Problem dims (fixed by setup_inputs)
#define T_TOK 8192
#define D_DIM 2048
#define E_EXP 8
#define H_DIM 2048
#define C_CAP 2048
#define B_BATCH 4
#define S_SEQ 2048

// ---------------- device scratch (allocation-free) ----------------
__device__ int   g_e0[T_TOK], g_e1[T_TOK];
__device__ float g_g0[T_TOK], g_g1[T_TOK];
__device__ int   g_p0[T_TOK], g_p1[T_TOK];
__device__ int   g_src[E_EXP * C_CAP];
__device__ float g_w2sum[E_EXP * H_DIM];
__device__ float g_b2sum[E_EXP];
__device__ float g_rowsum[E_EXP * C_CAP];
__device__ float g_y[T_TOK];
// W1 transposed [e][h][d], split into bf16 hi/lo
__device__ __align__(16) __nv_bfloat16 g_w1h[(size_t)E_EXP * H_DIM * D_DIM];
__device__ __align__(16) __nv_bfloat16 g_w1l[(size_t)E_EXP * H_DIM * D_DIM];

// ---------------- helpers ----------------
__device__ __forceinline__ uint32_t smem_u32(const void* p) {
    uint32_t a;
    asm("{ .reg .u64 t; cvta.to.shared.u64 t, %1; cvt.u32.u64 %0, t; }" : "=r"(a) : "l"(p));
    return a;
}
__device__ __forceinline__ uint32_t pack_pair(float a, float b, uint32_t& lo) {
    __nv_bfloat16 ha = __float2bfloat16(a);
    __nv_bfloat16 hb = __float2bfloat16(b);
    float ra = a - __bfloat162float(ha);
    float rb = b - __bfloat162float(hb);
    __nv_bfloat16 la = __float2bfloat16(ra);
    __nv_bfloat16 lb = __float2bfloat16(rb);
    lo = (uint32_t)__bfloat16_as_ushort(la) | ((uint32_t)__bfloat16_as_ushort(lb) << 16);
    return (uint32_t)__bfloat16_as_ushort(ha) | ((uint32_t)__bfloat16_as_ushort(hb) << 16);
}
#define LDM4(d, a) \
    asm volatile("ldmatrix.sync.aligned.m8n8.x4.shared.b16 {%0,%1,%2,%3}, [%4];" \
        : "=r"((d)[0]), "=r"((d)[1]), "=r"((d)[2]), "=r"((d)[3]) : "r"(a))
#define MMA(c, a, b) \
    asm volatile("mma.sync.aligned.m16n8k16.row.col.f32.bf16.bf16.f32 " \
        "{%0,%1,%2,%3},{%4,%5,%6,%7},{%8,%9},{%0,%1,%2,%3};" \
        : "+f"((c)[0]), "+f"((c)[1]), "+f"((c)[2]), "+f"((c)[3]) \
        : "r"((a)[0]), "r"((a)[1]), "r"((a)[2]), "r"((a)[3]), "r"((b)[0]), "r"((b)[1]))
#define CP16(dst, src) \
    asm volatile("cp.async.ca.shared.global [%0], [%1], 16;" :: "r"(dst), "l"(src) : "memory")
#define CP_COMMIT() asm volatile("cp.async.commit_group;" ::: "memory")
#define CP_WAIT0()  asm volatile("cp.async.wait_group 0;" ::: "memory")

// ---------------- K0: per-launch reset ----------------
__global__ void k_init() {
    int i = blockIdx.x * blockDim.x + threadIdx.x;
    if (i < E_EXP * C_CAP) {
        g_src[i] = -1;
        g_rowsum[i] = 0.f;
    }
}

// ---------------- K1: gating (exact fp32 routing) ----------------
__global__ void k_gate(const float* __restrict__ x, const float* __restrict__ Wg) {
    int warp = threadIdx.x >> 5;
    int lane = threadIdx.x & 31;
    int tok = blockIdx.x * 8 + warp;
    if (tok >= T_TOK) return;
    const float* xr = x + (size_t)tok * D_DIM;

    float acc[8];
#pragma unroll
    for (int e = 0; e < 8; e++) acc[e] = 0.f;
    for (int k = lane; k < D_DIM; k += 32) {
        float xv = xr[k];
        const float* wr = Wg + (size_t)k * 8;
        float4 w0 = *(const float4*)(wr);
        float4 w1 = *(const float4*)(wr + 4);
        acc[0] = fmaf(xv, w0.x, acc[0]);
        acc[1] = fmaf(xv, w0.y, acc[1]);
        acc[2] = fmaf(xv, w0.z, acc[2]);
        acc[3] = fmaf(xv, w0.w, acc[3]);
        acc[4] = fmaf(xv, w1.x, acc[4]);
        acc[5] = fmaf(xv, w1.y, acc[5]);
        acc[6] = fmaf(xv, w1.z, acc[6]);
        acc[7] = fmaf(xv, w1.w, acc[7]);
    }
#pragma unroll
    for (int e = 0; e < 8; e++) {
#pragma unroll
        for (int off = 16; off > 0; off >>= 1)
            acc[e] += __shfl_xor_sync(0xffffffffu, acc[e], off);
    }
    if (lane == 0) {
        float l0 = acc[0]; int i0 = 0;
#pragma unroll
        for (int e = 1; e < 8; e++) if (acc[e] > l0) { l0 = acc[e]; i0 = e; }
        float l1 = -INFINITY; int i1 = 0;
#pragma unroll
        for (int e = 0; e < 8; e++) if (e != i0 && acc[e] > l1) { l1 = acc[e]; i1 = e; }
        float g0 = 1.f / (1.f + __expf(l1 - l0));
        g_e0[tok] = i0; g_e1[tok] = i1;
        g_g0[tok] = g0; g_g1[tok] = 1.f - g0;
    }
}

// ---------------- K2: dispatch scan (single block) ----------------
#define SCAN_T 512
#define TOK_PER_T (T_TOK / SCAN_T)
__global__ void k_scan() {
    __shared__ int shCnt[SCAN_T * 8];
    __shared__ int shScan[SCAN_T * 8];
    __shared__ int shTot[8];
    int t = threadIdx.x;

    for (int e = 0; e < 8; e++) shCnt[t * 8 + e] = 0;
    for (int i = 0; i < TOK_PER_T; i++) {
        int tok = t * TOK_PER_T + i;
        shCnt[t * 8 + g_e0[tok]]++;
    }
    for (int e = 0; e < 8; e++) shScan[t * 8 + e] = shCnt[t * 8 + e];
    __syncthreads();
    for (int s = 1; s < SCAN_T; s <<= 1) {
        int v[8];
        if (t >= s) { for (int e = 0; e < 8; e++) v[e] = shScan[(t - s) * 8 + e]; }
        __syncthreads();
        if (t >= s) { for (int e = 0; e < 8; e++) shScan[t * 8 + e] += v[e]; }
        __syncthreads();
    }
    if (t == 0) { for (int e = 0; e < 8; e++) shTot[e] = shScan[(SCAN_T - 1) * 8 + e]; }
    for (int e = 0; e < 8; e++) shCnt[t * 8 + e] = shScan[t * 8 + e] - shCnt[t * 8 + e];
    __syncthreads();
    for (int i = 0; i < TOK_PER_T; i++) {
        int tok = t * TOK_PER_T + i;
        int e = g_e0[tok];
        int pos = shCnt[t * 8 + e]++;
        if (pos < C_CAP) { g_p0[tok] = pos; g_src[e * C_CAP + pos] = tok; }
        else             { g_p0[tok] = -1; }
    }
    __syncthreads();

    for (int e = 0; e < 8; e++) shCnt[t * 8 + e] = 0;
    for (int i = 0; i < TOK_PER_T; i++) {
        int tok = t * TOK_PER_T + i;
        shCnt[t * 8 + g_e1[tok]]++;
    }
    for (int e = 0; e < 8; e++) shScan[t * 8 + e] = shCnt[t * 8 + e];
    __syncthreads();
    for (int s = 1; s < SCAN_T; s <<= 1) {
        int v[8];
        if (t >= s) { for (int e = 0; e < 8; e++) v[e] = shScan[(t - s) * 8 + e]; }
        __syncthreads();
        if (t >= s) { for (int e = 0; e < 8; e++) shScan[t * 8 + e] += v[e]; }
        __syncthreads();
    }
    for (int e = 0; e < 8; e++)
        shCnt[t * 8 + e] = shScan[t * 8 + e] - shCnt[t * 8 + e] + shTot[e];
    __syncthreads();
    for (int i = 0; i < TOK_PER_T; i++) {
        int tok = t * TOK_PER_T + i;
        int e = g_e1[tok];
        int pos = shCnt[t * 8 + e]++;
        if (pos < C_CAP) { g_p1[tok] = pos; g_src[e * C_CAP + pos] = tok; }
        else             { g_p1[tok] = -1; }
    }
}

// ---------------- K3a: w2sum ----------------
__global__ void k_w2sum(const float* __restrict__ W2) {
    int gw = (blockIdx.x * blockDim.x + threadIdx.x) >> 5;
    int lane = threadIdx.x & 31;
    if (gw >= E_EXP * H_DIM) return;
    const float* r = W2 + (size_t)gw * D_DIM;
    float s = 0.f;
    for (int k = lane * 4; k < D_DIM; k += 128) {
        float4 v = *(const float4*)(r + k);
        s += (v.x + v.y) + (v.z + v.w);
    }
#pragma unroll
    for (int off = 16; off > 0; off >>= 1) s += __shfl_xor_sync(0xffffffffu, s, off);
    if (lane == 0) g_w2sum[gw] = s;
}

// ---------------- K3b: b2sum ----------------
__global__ void k_b2sum(const float* __restrict__ b2) {
    int w = threadIdx.x >> 5, lane = threadIdx.x & 31;
    if (w >= E_EXP) return;
    float s = 0.f;
    for (int k = lane; k < D_DIM; k += 32) s += b2[(size_t)w * D_DIM + k];
#pragma unroll
    for (int off = 16; off > 0; off >>= 1) s += __shfl_xor_sync(0xffffffffu, s, off);
    if (lane == 0) g_b2sum[w] = s;
}

// ---------------- K3c: transpose + split W1 -> [E][H][D] bf16 hi/lo ----------------
__global__ void k_w1t(const float* __restrict__ W1) {
    __shared__ float tl[32][33];
    int e = blockIdx.z;
    int h0 = blockIdx.x * 32, d0 = blockIdx.y * 32;
    int tx = threadIdx.x, ty = threadIdx.y;
#pragma unroll
    for (int i = 0; i < 4; i++) {
        int d = d0 + ty + i * 8;
        tl[ty + i * 8][tx] = W1[((size_t)e * D_DIM + d) * H_DIM + h0 + tx];
    }
    __syncthreads();
#pragma unroll
    for (int i = 0; i < 4; i++) {
        int h = h0 + ty + i * 8;
        float v = tl[tx][ty + i * 8];
        __nv_bfloat16 hh = __float2bfloat16(v);
        float r = v - __bfloat162float(hh);
        __nv_bfloat16 ll = __float2bfloat16(r);
        size_t o = ((size_t)e * H_DIM + h) * D_DIM + d0 + tx;
        g_w1h[o] = hh;
        g_w1l[o] = ll;
    }
}

// ---------------- K4: HMMA fused expert GEMM + relu*w2sum epilogue ----------------
// Tile M=128 x N=128, BK=32 (2 k16 phases), 8 warps (2x4), 3-pass hi/lo bf16.
// smem: padded stride 40 bf16 (80B) per row, double-buffered, B via cp.async.
#define STRIDE_B 80
#define OFF_AH 0
#define OFF_AL 10240
#define OFF_BH 20480
#define OFF_BL 30720
#define STAGE  40960
#define OFF_W2 81920
#define OFF_B1 82432
#define SMEM_FFN 82944
#define NIT (D_DIM / 32)   // 64

__global__ void __launch_bounds__(256, 1) k_ffn(const float* __restrict__ x,
                                                const float* __restrict__ b1) {
    extern __shared__ char smem[];
    const uint32_t sbase = smem_u32(smem);
    const int tid = threadIdx.x;
    const int lane = tid & 31, wid = tid >> 5;
    const int wm = wid >> 2, wn = wid & 3;
    const int e = blockIdx.z;
    const int row0 = blockIdx.y * 128;
    const int col0 = blockIdx.x * 128;

    float* sW2 = (float*)(smem + OFF_W2);
    float* sB1 = (float*)(smem + OFF_B1);
    if (tid < 128) {
        sW2[tid] = g_w2sum[e * H_DIM + col0 + tid];
        sB1[tid] = b1[(size_t)e * H_DIM + col0 + tid];
    }

    // loader assignment: 2 threads per row, 16 elements each
    const int lr = tid >> 1;
    const int kseg = tid & 1;
    const int srcTok = g_src[e * C_CAP + row0 + lr];
    const bool aval = srcTok >= 0;
    const float* aPtr = x + (size_t)(aval ? srcTok : 0) * D_DIM + kseg * 16;
    const size_t bOff = (size_t)(e * H_DIM + col0 + lr) * D_DIM + kseg * 16;
    const __nv_bfloat16* bhPtr = g_w1h + bOff;
    const __nv_bfloat16* blPtr = g_w1l + bOff;
    const int aByte = lr * STRIDE_B + kseg * 32;

    float ar[16];
    float acc[4][4][4];
#pragma unroll
    for (int i = 0; i < 4; i++)
#pragma unroll
        for (int j = 0; j < 4; j++)
#pragma unroll
            for (int q = 0; q < 4; q++) acc[i][j][q] = 0.f;

    // ---- prologue: tile 0 ----
    if (aval) {
#pragma unroll
        for (int q = 0; q < 4; q++) *(float4*)(ar + q * 4) = *(const float4*)(aPtr + q * 4);
    }
    {
        uint32_t d = sbase + OFF_BH + aByte;
        const char* s = (const char*)bhPtr;
        CP16(d, s); CP16(d + 16, s + 16);
        uint32_t d2 = sbase + OFF_BL + aByte;
        const char* s2 = (const char*)blPtr;
        CP16(d2, s2); CP16(d2 + 16, s2 + 16);
        CP_COMMIT();
    }
    {
        uint32_t hi[8], lo[8];
#pragma unroll
        for (int q = 0; q < 8; q++)
            hi[q] = aval ? pack_pair(ar[2 * q], ar[2 * q + 1], lo[q]) : (lo[q] = 0u, 0u);
        char* pa = smem + OFF_AH + aByte;
        *(uint4*)pa = *(uint4*)hi; *(uint4*)(pa + 16) = *(uint4*)(hi + 4);
        char* pl = smem + OFF_AL + aByte;
        *(uint4*)pl = *(uint4*)lo; *(uint4*)(pl + 16) = *(uint4*)(lo + 4);
    }
    CP_WAIT0();
    __syncthreads();

    // fragment base addresses (lane-dependent part)
    const uint32_t aFragOff = (wm * 64 + (lane & 15)) * STRIDE_B + ((lane >> 4) << 4);
    const uint32_t bFragOff = (wn * 32 + (lane & 15)) * STRIDE_B + ((lane >> 4) << 4);

    for (int it = 0; it < NIT; it++) {
        const int st = it & 1;
        const bool nxt = (it + 1 < NIT);
        if (nxt) {
            const int co = (it + 1) * 32;
            if (aval) {
#pragma unroll
                for (int q = 0; q < 4; q++)
                    *(float4*)(ar + q * 4) = *(const float4*)(aPtr + co + q * 4);
            }
            uint32_t sb = sbase + (st ^ 1) * STAGE;
            uint32_t d = sb + OFF_BH + aByte;
            const char* s = (const char*)(bhPtr + co);
            CP16(d, s); CP16(d + 16, s + 16);
            uint32_t d2 = sb + OFF_BL + aByte;
            const char* s2 = (const char*)(blPtr + co);
            CP16(d2, s2); CP16(d2 + 16, s2 + 16);
            CP_COMMIT();
        }

        // ---- compute on buffer st ----
        {
            const uint32_t aB = sbase + st * STAGE + OFF_AH + aFragOff;
            const uint32_t bB = sbase + st * STAGE + OFF_BH + bFragOff;
#pragma unroll
            for (int kh = 0; kh < 2; kh++) {
                uint32_t ah[4][4], al[4][4], bh[4][2], bl[4][2];
#pragma unroll
                for (int ma = 0; ma < 4; ma++) {
                    LDM4(ah[ma], aB + ma * (16 * STRIDE_B) + kh * 32);
                    LDM4(al[ma], aB + (OFF_AL - OFF_AH) + ma * (16 * STRIDE_B) + kh * 32);
                }
#pragma unroll
                for (int np = 0; np < 2; np++) {
                    uint32_t tr[4];
                    LDM4(tr, bB + np * (16 * STRIDE_B) + kh * 32);
                    bh[np * 2][0] = tr[0]; bh[np * 2][1] = tr[2];
                    bh[np * 2 + 1][0] = tr[1]; bh[np * 2 + 1][1] = tr[3];
                    LDM4(tr, bB + (OFF_BL - OFF_BH) + np * (16 * STRIDE_B) + kh * 32);
                    bl[np * 2][0] = tr[0]; bl[np * 2][1] = tr[2];
                    bl[np * 2 + 1][0] = tr[1]; bl[np * 2 + 1][1] = tr[3];
                }
#pragma unroll
                for (int ma = 0; ma < 4; ma++)
#pragma unroll
                    for (int na = 0; na < 4; na++) {
                        MMA(acc[ma][na], ah[ma], bh[na]);
                        MMA(acc[ma][na], al[ma], bh[na]);
                        MMA(acc[ma][na], ah[ma], bl[na]);
                    }
            }
        }

        if (nxt) {
            uint32_t hi[8], lo[8];
#pragma unroll
            for (int q = 0; q < 8; q++)
                hi[q] = aval ? pack_pair(ar[2 * q], ar[2 * q + 1], lo[q]) : (lo[q] = 0u, 0u);
            char* sb = smem + (st ^ 1) * STAGE;
            char* pa = sb + OFF_AH + aByte;
            *(uint4*)pa = *(uint4*)hi; *(uint4*)(pa + 16) = *(uint4*)(hi + 4);
            char* pl = sb + OFF_AL + aByte;
            *(uint4*)pl = *(uint4*)lo; *(uint4*)(pl + 16) = *(uint4*)(lo + 4);
            CP_WAIT0();
        }
        __syncthreads();
    }

    // ---- epilogue: relu(z + b1) * w2sum, reduce over N, one atomic per row ----
#pragma unroll
    for (int ma = 0; ma < 4; ma++) {
        float s0 = 0.f, s1 = 0.f;
#pragma unroll
        for (int na = 0; na < 4; na++) {
            int cb = wn * 32 + na * 8 + (lane & 3) * 2;
            float w0 = sW2[cb], w1v = sW2[cb + 1];
            float bb0 = sB1[cb], bb1 = sB1[cb + 1];
            s0 += fmaxf(acc[ma][na][0] + bb0, 0.f) * w0
                + fmaxf(acc[ma][na][1] + bb1, 0.f) * w1v;
            s1 += fmaxf(acc[ma][na][2] + bb0, 0.f) * w0
                + fmaxf(acc[ma][na][3] + bb1, 0.f) * w1v;
        }
        s0 += __shfl_xor_sync(0xffffffffu, s0, 1);
        s0 += __shfl_xor_sync(0xffffffffu, s0, 2);
        s1 += __shfl_xor_sync(0xffffffffu, s1, 1);
        s1 += __shfl_xor_sync(0xffffffffu, s1, 2);
        if ((lane & 3) == 0) {
            int r = row0 + wm * 64 + ma * 16 + (lane >> 2);
            atomicAdd(&g_rowsum[e * C_CAP + r], s0);
            atomicAdd(&g_rowsum[e * C_CAP + r + 8], s1);
        }
    }
}

// ---------------- K5: combine ----------------
__global__ void k_combine() {
    int t = blockIdx.x * blockDim.x + threadIdx.x;
    if (t >= T_TOK) return;
    float y = 0.f;
    int p0 = g_p0[t];
    if (p0 >= 0) {
        int e = g_e0[t];
        y += g_g0[t] * (g_rowsum[e * C_CAP + p0] + g_b2sum[e]);
    }
    int p1 = g_p1[t];
    if (p1 >= 0) {
        int e = g_e1[t];
        y += g_g1[t] * (g_rowsum[e * C_CAP + p1] + g_b2sum[e]);
    }
    g_y[t] = y;
}

// ---------------- K6: log_softmax over S per batch ----------------
__global__ void k_lsm(float* __restrict__ out) {
    __shared__ float red[256];
    int b = blockIdx.x, tid = threadIdx.x;
    const float* yr = g_y + (size_t)b * S_SEQ;

    float m = -INFINITY;
    for (int s = tid; s < S_SEQ; s += 256) m = fmaxf(m, yr[s]);
    red[tid] = m; __syncthreads();
    for (int off = 128; off > 0; off >>= 1) {
        if (tid < off) red[tid] = fmaxf(red[tid], red[tid + off]);
        __syncthreads();
    }
    m = red[0]; __syncthreads();

    float sum = 0.f;
    for (int s = tid; s < S_SEQ; s += 256) sum += expf(yr[s] - m);
    red[tid] = sum; __syncthreads();
    for (int off = 128; off > 0; off >>= 1) {
        if (tid < off) red[tid] += red[tid + off];
        __syncthreads();
    }
    float lse = m + logf(red[0]);

    for (int s = tid; s < S_SEQ; s += 256)
        out[(size_t)b * S_SEQ + s] = yr[s] - lse;
}

// ---------------- launch ----------------
extern "C" void kernel_launch(void* const* d_in, const int* in_sizes, int n_in,
                              void* d_out, int out_size) {
    const float* x  = (const float*)d_in[0];
    const float* Wg = (const float*)d_in[1];
    const float* W1 = (const float*)d_in[2];
    const float* b1 = (const float*)d_in[3];
    const float* W2 = (const float*)d_in[4];
    const float* b2 = (const float*)d_in[5];
    float* out = (float*)d_out;

    cudaFuncSetAttribute(k_ffn, cudaFuncAttributeMaxDynamicSharedMemorySize, SMEM_FFN);

    k_init<<<(E_EXP * C_CAP + 255) / 256, 256>>>();
    k_w1t<<<dim3(H_DIM / 32, D_DIM / 32, E_EXP), dim3(32, 8)>>>(W1);
    k_gate<<<T_TOK / 8, 256>>>(x, Wg);
    k_scan<<<1, SCAN_T>>>();
    k_w2sum<<<(E_EXP * H_DIM) / 8, 256>>>(W2);
    k_b2sum<<<1, 256>>>(b2);
    k_ffn<<<dim3(H_DIM / 128, C_CAP / 128, E_EXP), 256, SMEM_FFN>>>(x, b1);
    k_combine<<<T_TOK / 256, 256>>>();
    k_lsm<<<B_BATCH, 256>>>(out);
}

// round 5
// speedup vs baseline: 2.8784x; 1.7444x over previous
#include <cuda_runtime.h>
#include <cuda_fp16.h>
#include <math.h>
#include <stdint.h>

// Problem dims (fixed by setup_inputs)
#define T_TOK 8192
#define D_DIM 2048
#define E_EXP 8
#define H_DIM 2048
#define C_CAP 2048
#define B_BATCH 4
#define S_SEQ 2048

// ---------------- device scratch (allocation-free) ----------------
__device__ int   g_e0[T_TOK], g_e1[T_TOK];
__device__ float g_g0[T_TOK], g_g1[T_TOK];
__device__ int   g_p0[T_TOK], g_p1[T_TOK];
__device__ int   g_src[E_EXP * C_CAP];
__device__ float g_w2sum[E_EXP * H_DIM];
__device__ float g_b2sum[E_EXP];
__device__ float g_rowsum[E_EXP * C_CAP];
__device__ float g_y[T_TOK];
// fp16 copies: x, and W1 transposed [e][h][d] scaled by 2048 split hi/lo
__device__ __align__(16) __half g_xh[(size_t)T_TOK * D_DIM];
__device__ __align__(16) __half g_w1h[(size_t)E_EXP * H_DIM * D_DIM];
__device__ __align__(16) __half g_w1l[(size_t)E_EXP * H_DIM * D_DIM];

#define W1_SCALE 2048.0f
#define W1_INV   (1.0f / 2048.0f)

// ---------------- helpers ----------------
__device__ __forceinline__ uint32_t smem_u32(const void* p) {
    uint32_t a;
    asm("{ .reg .u64 t; cvta.to.shared.u64 t, %1; cvt.u32.u64 %0, t; }" : "=r"(a) : "l"(p));
    return a;
}
#define LDM4(d, a) \
    asm volatile("ldmatrix.sync.aligned.m8n8.x4.shared.b16 {%0,%1,%2,%3}, [%4];" \
        : "=r"((d)[0]), "=r"((d)[1]), "=r"((d)[2]), "=r"((d)[3]) : "r"(a))
#define MMA(c, a, b) \
    asm volatile("mma.sync.aligned.m16n8k16.row.col.f32.f16.f16.f32 " \
        "{%0,%1,%2,%3},{%4,%5,%6,%7},{%8,%9},{%0,%1,%2,%3};" \
        : "+f"((c)[0]), "+f"((c)[1]), "+f"((c)[2]), "+f"((c)[3]) \
        : "r"((a)[0]), "r"((a)[1]), "r"((a)[2]), "r"((a)[3]), "r"((b)[0]), "r"((b)[1]))
#define CP16(dst, src) \
    asm volatile("cp.async.ca.shared.global [%0], [%1], 16;" :: "r"(dst), "l"(src) : "memory")
#define CP16Z(dst, src, n) \
    asm volatile("cp.async.ca.shared.global [%0], [%1], 16, %2;" :: "r"(dst), "l"(src), "r"(n) : "memory")
#define CP_COMMIT() asm volatile("cp.async.commit_group;" ::: "memory")
#define CP_WAIT2()  asm volatile("cp.async.wait_group 2;" ::: "memory")

// ---------------- K0: per-launch reset ----------------
__global__ void k_init() {
    int i = blockIdx.x * blockDim.x + threadIdx.x;
    if (i < E_EXP * C_CAP) {
        g_src[i] = -1;
        g_rowsum[i] = 0.f;
    }
}

// ---------------- K1: gating (exact fp32 routing) ----------------
__global__ void k_gate(const float* __restrict__ x, const float* __restrict__ Wg) {
    int warp = threadIdx.x >> 5;
    int lane = threadIdx.x & 31;
    int tok = blockIdx.x * 8 + warp;
    if (tok >= T_TOK) return;
    const float* xr = x + (size_t)tok * D_DIM;

    float acc[8];
#pragma unroll
    for (int e = 0; e < 8; e++) acc[e] = 0.f;
    for (int k = lane; k < D_DIM; k += 32) {
        float xv = xr[k];
        const float* wr = Wg + (size_t)k * 8;
        float4 w0 = *(const float4*)(wr);
        float4 w1 = *(const float4*)(wr + 4);
        acc[0] = fmaf(xv, w0.x, acc[0]);
        acc[1] = fmaf(xv, w0.y, acc[1]);
        acc[2] = fmaf(xv, w0.z, acc[2]);
        acc[3] = fmaf(xv, w0.w, acc[3]);
        acc[4] = fmaf(xv, w1.x, acc[4]);
        acc[5] = fmaf(xv, w1.y, acc[5]);
        acc[6] = fmaf(xv, w1.z, acc[6]);
        acc[7] = fmaf(xv, w1.w, acc[7]);
    }
#pragma unroll
    for (int e = 0; e < 8; e++) {
#pragma unroll
        for (int off = 16; off > 0; off >>= 1)
            acc[e] += __shfl_xor_sync(0xffffffffu, acc[e], off);
    }
    if (lane == 0) {
        float l0 = acc[0]; int i0 = 0;
#pragma unroll
        for (int e = 1; e < 8; e++) if (acc[e] > l0) { l0 = acc[e]; i0 = e; }
        float l1 = -INFINITY; int i1 = 0;
#pragma unroll
        for (int e = 0; e < 8; e++) if (e != i0 && acc[e] > l1) { l1 = acc[e]; i1 = e; }
        float g0 = 1.f / (1.f + __expf(l1 - l0));
        g_e0[tok] = i0; g_e1[tok] = i1;
        g_g0[tok] = g0; g_g1[tok] = 1.f - g0;
    }
}

// ---------------- K2: dispatch scan (single block, shfl-based) ----------------
// Order: all choice-0 assignments in token order, then all choice-1 (GShard k-major).
__global__ void k_scan() {
    __shared__ int warpOff[8][8];   // per-warp exclusive offsets [warp][expert]
    __shared__ int shTot[8];
    const int tid = threadIdx.x, lane = tid & 31, w = tid >> 5;
    const int base = tid * 32;

    // ======== choice 0 ========
    int cnt[8];
#pragma unroll
    for (int e = 0; e < 8; e++) cnt[e] = 0;
    for (int i = 0; i < 32; i++) cnt[g_e0[base + i]]++;
    int inc[8];
#pragma unroll
    for (int e = 0; e < 8; e++) inc[e] = cnt[e];
#pragma unroll
    for (int off = 1; off < 32; off <<= 1) {
#pragma unroll
        for (int e = 0; e < 8; e++) {
            int v = __shfl_up_sync(0xffffffffu, inc[e], off);
            if (lane >= off) inc[e] += v;
        }
    }
    if (lane == 31) {
#pragma unroll
        for (int e = 0; e < 8; e++) warpOff[w][e] = inc[e];   // warp totals
    }
    __syncthreads();
    if (w == 0 && lane < 8) {
        int s = 0;
        for (int ww = 0; ww < 8; ww++) {
            int t = warpOff[ww][lane];
            warpOff[ww][lane] = s;
            s += t;
        }
        shTot[lane] = s;
    }
    __syncthreads();
    int run[8];
#pragma unroll
    for (int e = 0; e < 8; e++) run[e] = warpOff[w][e] + inc[e] - cnt[e];
    for (int i = 0; i < 32; i++) {
        int tok = base + i;
        int e = g_e0[tok];
        int pos = run[e]++;
        if (pos < C_CAP) { g_p0[tok] = pos; g_src[e * C_CAP + pos] = tok; }
        else             { g_p0[tok] = -1; }
    }
    __syncthreads();

    // ======== choice 1 (base = total choice-0 counts) ========
#pragma unroll
    for (int e = 0; e < 8; e++) cnt[e] = 0;
    for (int i = 0; i < 32; i++) cnt[g_e1[base + i]]++;
#pragma unroll
    for (int e = 0; e < 8; e++) inc[e] = cnt[e];
#pragma unroll
    for (int off = 1; off < 32; off <<= 1) {
#pragma unroll
        for (int e = 0; e < 8; e++) {
            int v = __shfl_up_sync(0xffffffffu, inc[e], off);
            if (lane >= off) inc[e] += v;
        }
    }
    if (lane == 31) {
#pragma unroll
        for (int e = 0; e < 8; e++) warpOff[w][e] = inc[e];
    }
    __syncthreads();
    if (w == 0 && lane < 8) {
        int s = 0;
        for (int ww = 0; ww < 8; ww++) {
            int t = warpOff[ww][lane];
            warpOff[ww][lane] = s;
            s += t;
        }
    }
    __syncthreads();
#pragma unroll
    for (int e = 0; e < 8; e++) run[e] = shTot[e] + warpOff[w][e] + inc[e] - cnt[e];
    for (int i = 0; i < 32; i++) {
        int tok = base + i;
        int e = g_e1[tok];
        int pos = run[e]++;
        if (pos < C_CAP) { g_p1[tok] = pos; g_src[e * C_CAP + pos] = tok; }
        else             { g_p1[tok] = -1; }
    }
}

// ---------------- K3a: w2sum ----------------
__global__ void k_w2sum(const float* __restrict__ W2) {
    int gw = (blockIdx.x * blockDim.x + threadIdx.x) >> 5;
    int lane = threadIdx.x & 31;
    if (gw >= E_EXP * H_DIM) return;
    const float* r = W2 + (size_t)gw * D_DIM;
    float s = 0.f;
    for (int k = lane * 4; k < D_DIM; k += 128) {
        float4 v = *(const float4*)(r + k);
        s += (v.x + v.y) + (v.z + v.w);
    }
#pragma unroll
    for (int off = 16; off > 0; off >>= 1) s += __shfl_xor_sync(0xffffffffu, s, off);
    if (lane == 0) g_w2sum[gw] = s;
}

// ---------------- K3b: b2sum ----------------
__global__ void k_b2sum(const float* __restrict__ b2) {
    int w = threadIdx.x >> 5, lane = threadIdx.x & 31;
    if (w >= E_EXP) return;
    float s = 0.f;
    for (int k = lane; k < D_DIM; k += 32) s += b2[(size_t)w * D_DIM + k];
#pragma unroll
    for (int off = 16; off > 0; off >>= 1) s += __shfl_xor_sync(0xffffffffu, s, off);
    if (lane == 0) g_b2sum[w] = s;
}

// ---------------- K3c: transpose + scale + split W1 -> [E][H][D] fp16 hi/lo ----------------
__global__ void k_w1t(const float* __restrict__ W1) {
    __shared__ float tl[32][33];
    int e = blockIdx.z;
    int h0 = blockIdx.x * 32, d0 = blockIdx.y * 32;
    int tx = threadIdx.x, ty = threadIdx.y;
#pragma unroll
    for (int i = 0; i < 4; i++) {
        int d = d0 + ty + i * 8;
        tl[ty + i * 8][tx] = W1[((size_t)e * D_DIM + d) * H_DIM + h0 + tx];
    }
    __syncthreads();
#pragma unroll
    for (int i = 0; i < 4; i++) {
        int h = h0 + ty + i * 8;
        float v = tl[tx][ty + i * 8] * W1_SCALE;
        __half hh = __float2half_rn(v);
        float r = v - __half2float(hh);
        __half ll = __float2half_rn(r);
        size_t o = ((size_t)e * H_DIM + h) * D_DIM + d0 + tx;
        g_w1h[o] = hh;
        g_w1l[o] = ll;
    }
}

// ---------------- K3d: x -> fp16 ----------------
__global__ void k_xh(const float* __restrict__ x) {
    size_t i = ((size_t)blockIdx.x * 256 + threadIdx.x) * 4;
    float4 v = *(const float4*)(x + i);
    *(__half2*)(g_xh + i)     = __floats2half2_rn(v.x, v.y);
    *(__half2*)(g_xh + i + 2) = __floats2half2_rn(v.z, v.w);
}

// ---------------- K4: HMMA fused expert GEMM + relu*w2sum epilogue ----------------
// Tile M=128 x N=128, BK=32, 8 warps (2x4 of 64x32), 2-pass: z = A*(Bh + Bl).
// 4-stage cp.async pipeline, padded 80B row stride.
#define STRIDE 80
#define OFF_A  0
#define OFF_BH 10240
#define OFF_BL 20480
#define STAGE_SZ 30720
#define NSTAGE 4
#define OFF_W2 (STAGE_SZ * NSTAGE)            // 122880
#define OFF_B1 (OFF_W2 + 512)
#define SMEM_FFN (OFF_B1 + 512)               // 123904
#define NIT (D_DIM / 32)                      // 64

__global__ void __launch_bounds__(256, 1) k_ffn(const float* __restrict__ b1) {
    extern __shared__ char smem[];
    const uint32_t sbase = smem_u32(smem);
    const int tid = threadIdx.x;
    const int lane = tid & 31, wid = tid >> 5;
    const int wm = wid >> 2, wn = wid & 3;
    const int e = blockIdx.z;
    const int row0 = blockIdx.y * 128;
    const int col0 = blockIdx.x * 128;

    float* sW2 = (float*)(smem + OFF_W2);
    float* sB1 = (float*)(smem + OFF_B1);
    if (tid < 128) {
        sW2[tid] = g_w2sum[e * H_DIM + col0 + tid];
        sB1[tid] = b1[(size_t)e * H_DIM + col0 + tid];
    }

    // loader: 2 threads per row, 32B (16 fp16) each
    const int lr = tid >> 1;
    const int kseg = tid & 1;
    const int srcTok = g_src[e * C_CAP + row0 + lr];
    const int aPred = (srcTok >= 0) ? 16 : 0;       // cp.async src-size (0 => zero-fill)
    const __half* aPtr = g_xh + (size_t)(srcTok >= 0 ? srcTok : 0) * D_DIM + kseg * 16;
    const size_t bOff = (size_t)(e * H_DIM + col0 + lr) * D_DIM + kseg * 16;
    const __half* bhPtr = g_w1h + bOff;
    const __half* blPtr = g_w1l + bOff;
    const int ldByte = lr * STRIDE + kseg * 32;

    float acc[4][4][4];
#pragma unroll
    for (int i = 0; i < 4; i++)
#pragma unroll
        for (int j = 0; j < 4; j++)
#pragma unroll
            for (int q = 0; q < 4; q++) acc[i][j][q] = 0.f;

    auto issue = [&](int it, int st) {
        const uint32_t sb = sbase + st * STAGE_SZ;
        const int co = it * 32;
        CP16Z(sb + OFF_A + ldByte,      aPtr + co,     aPred);
        CP16Z(sb + OFF_A + ldByte + 16, aPtr + co + 8, aPred);
        CP16(sb + OFF_BH + ldByte,      bhPtr + co);
        CP16(sb + OFF_BH + ldByte + 16, bhPtr + co + 8);
        CP16(sb + OFF_BL + ldByte,      blPtr + co);
        CP16(sb + OFF_BL + ldByte + 16, blPtr + co + 8);
    };

    // prologue: stages 0..2
    issue(0, 0); CP_COMMIT();
    issue(1, 1); CP_COMMIT();
    issue(2, 2); CP_COMMIT();

    const uint32_t aFragOff = (wm * 64 + (lane & 15)) * STRIDE + ((lane >> 4) << 4);
    const uint32_t bFragOff = (wn * 32 + (lane & 15)) * STRIDE + ((lane >> 4) << 4);

    for (int it = 0; it < NIT; it++) {
        const int st = it & (NSTAGE - 1);
        CP_WAIT2();
        __syncthreads();
        if (it + 3 < NIT) issue(it + 3, (it + 3) & (NSTAGE - 1));
        CP_COMMIT();

        const uint32_t aB = sbase + st * STAGE_SZ + OFF_A + aFragOff;
        const uint32_t bB = sbase + st * STAGE_SZ + OFF_BH + bFragOff;
#pragma unroll
        for (int kh = 0; kh < 2; kh++) {
            uint32_t a[4][4], bh[4][2], bl[4][2];
#pragma unroll
            for (int ma = 0; ma < 4; ma++)
                LDM4(a[ma], aB + ma * (16 * STRIDE) + kh * 32);
#pragma unroll
            for (int np = 0; np < 2; np++) {
                uint32_t tr[4];
                LDM4(tr, bB + np * (16 * STRIDE) + kh * 32);
                bh[np * 2][0] = tr[0];     bh[np * 2][1] = tr[2];
                bh[np * 2 + 1][0] = tr[1]; bh[np * 2 + 1][1] = tr[3];
                LDM4(tr, bB + (OFF_BL - OFF_BH) + np * (16 * STRIDE) + kh * 32);
                bl[np * 2][0] = tr[0];     bl[np * 2][1] = tr[2];
                bl[np * 2 + 1][0] = tr[1]; bl[np * 2 + 1][1] = tr[3];
            }
#pragma unroll
            for (int ma = 0; ma < 4; ma++)
#pragma unroll
                for (int na = 0; na < 4; na++) {
                    MMA(acc[ma][na], a[ma], bh[na]);
                    MMA(acc[ma][na], a[ma], bl[na]);
                }
        }
    }

    // ---- epilogue: relu(z*inv + b1) * w2sum, reduce over N, one atomic per row ----
#pragma unroll
    for (int ma = 0; ma < 4; ma++) {
        float s0 = 0.f, s1 = 0.f;
#pragma unroll
        for (int na = 0; na < 4; na++) {
            int cb = wn * 32 + na * 8 + (lane & 3) * 2;
            float w0 = sW2[cb], w1v = sW2[cb + 1];
            float bb0 = sB1[cb], bb1 = sB1[cb + 1];
            s0 += fmaxf(fmaf(acc[ma][na][0], W1_INV, bb0), 0.f) * w0
                + fmaxf(fmaf(acc[ma][na][1], W1_INV, bb1), 0.f) * w1v;
            s1 += fmaxf(fmaf(acc[ma][na][2], W1_INV, bb0), 0.f) * w0
                + fmaxf(fmaf(acc[ma][na][3], W1_INV, bb1), 0.f) * w1v;
        }
        s0 += __shfl_xor_sync(0xffffffffu, s0, 1);
        s0 += __shfl_xor_sync(0xffffffffu, s0, 2);
        s1 += __shfl_xor_sync(0xffffffffu, s1, 1);
        s1 += __shfl_xor_sync(0xffffffffu, s1, 2);
        if ((lane & 3) == 0) {
            int r = row0 + wm * 64 + ma * 16 + (lane >> 2);
            atomicAdd(&g_rowsum[e * C_CAP + r], s0);
            atomicAdd(&g_rowsum[e * C_CAP + r + 8], s1);
        }
    }
}

// ---------------- K5: combine ----------------
__global__ void k_combine() {
    int t = blockIdx.x * blockDim.x + threadIdx.x;
    if (t >= T_TOK) return;
    float y = 0.f;
    int p0 = g_p0[t];
    if (p0 >= 0) {
        int e = g_e0[t];
        y += g_g0[t] * (g_rowsum[e * C_CAP + p0] + g_b2sum[e]);
    }
    int p1 = g_p1[t];
    if (p1 >= 0) {
        int e = g_e1[t];
        y += g_g1[t] * (g_rowsum[e * C_CAP + p1] + g_b2sum[e]);
    }
    g_y[t] = y;
}

// ---------------- K6: log_softmax over S per batch ----------------
__global__ void k_lsm(float* __restrict__ out) {
    __shared__ float red[256];
    int b = blockIdx.x, tid = threadIdx.x;
    const float* yr = g_y + (size_t)b * S_SEQ;

    float m = -INFINITY;
    for (int s = tid; s < S_SEQ; s += 256) m = fmaxf(m, yr[s]);
    red[tid] = m; __syncthreads();
    for (int off = 128; off > 0; off >>= 1) {
        if (tid < off) red[tid] = fmaxf(red[tid], red[tid + off]);
        __syncthreads();
    }
    m = red[0]; __syncthreads();

    float sum = 0.f;
    for (int s = tid; s < S_SEQ; s += 256) sum += expf(yr[s] - m);
    red[tid] = sum; __syncthreads();
    for (int off = 128; off > 0; off >>= 1) {
        if (tid < off) red[tid] += red[tid + off];
        __syncthreads();
    }
    float lse = m + logf(red[0]);

    for (int s = tid; s < S_SEQ; s += 256)
        out[(size_t)b * S_SEQ + s] = yr[s] - lse;
}

// ---------------- launch ----------------
extern "C" void kernel_launch(void* const* d_in, const int* in_sizes, int n_in,
                              void* d_out, int out_size) {
    const float* x  = (const float*)d_in[0];
    const float* Wg = (const float*)d_in[1];
    const float* W1 = (const float*)d_in[2];
    const float* b1 = (const float*)d_in[3];
    const float* W2 = (const float*)d_in[4];
    const float* b2 = (const float*)d_in[5];
    float* out = (float*)d_out;

    cudaFuncSetAttribute(k_ffn, cudaFuncAttributeMaxDynamicSharedMemorySize, SMEM_FFN);

    k_init<<<(E_EXP * C_CAP + 255) / 256, 256>>>();
    k_w1t<<<dim3(H_DIM / 32, D_DIM / 32, E_EXP), dim3(32, 8)>>>(W1);
    k_xh<<<(T_TOK * (D_DIM / 4)) / 256, 256>>>(x);
    k_gate<<<T_TOK / 8, 256>>>(x, Wg);
    k_scan<<<1, 256>>>();
    k_w2sum<<<(E_EXP * H_DIM) / 8, 256>>>(W2);
    k_b2sum<<<1, 256>>>(b2);
    k_ffn<<<dim3(H_DIM / 128, C_CAP / 128, E_EXP), 256, SMEM_FFN>>>(b1);
    k_combine<<<T_TOK / 256, 256>>>();
    k_lsm<<<B_BATCH, 256>>>(out);
}

// round 6
// speedup vs baseline: 4.3963x; 1.5273x over previous
#include <cuda_runtime.h>
#include <cuda_fp16.h>
#include <math.h>
#include <stdint.h>

// Problem dims (fixed by setup_inputs)
#define T_TOK 8192
#define D_DIM 2048
#define E_EXP 8
#define H_DIM 2048
#define C_CAP 2048
#define B_BATCH 4
#define S_SEQ 2048

// ---------------- device scratch (allocation-free) ----------------
__device__ int   g_e0[T_TOK], g_e1[T_TOK];
__device__ float g_g0[T_TOK], g_g1[T_TOK];
__device__ int   g_p0[T_TOK], g_p1[T_TOK];
__device__ int   g_src[E_EXP * C_CAP];
__device__ float g_w2sum[E_EXP * H_DIM];
__device__ float g_b2sum[E_EXP];
__device__ float g_rowsum[E_EXP * C_CAP];
__device__ float g_y[T_TOK];
// fp16 copies: x (written by k_gate), W1 transposed [e][h][d]
__device__ __align__(16) __half g_xh[(size_t)T_TOK * D_DIM];
__device__ __align__(16) __half g_w1h[(size_t)E_EXP * H_DIM * D_DIM];

// ---------------- helpers ----------------
__device__ __forceinline__ uint32_t smem_u32(const void* p) {
    uint32_t a;
    asm("{ .reg .u64 t; cvta.to.shared.u64 t, %1; cvt.u32.u64 %0, t; }" : "=r"(a) : "l"(p));
    return a;
}
#define LDM4(d, a) \
    asm volatile("ldmatrix.sync.aligned.m8n8.x4.shared.b16 {%0,%1,%2,%3}, [%4];" \
        : "=r"((d)[0]), "=r"((d)[1]), "=r"((d)[2]), "=r"((d)[3]) : "r"(a))
#define MMA(c, a, b) \
    asm volatile("mma.sync.aligned.m16n8k16.row.col.f32.f16.f16.f32 " \
        "{%0,%1,%2,%3},{%4,%5,%6,%7},{%8,%9},{%0,%1,%2,%3};" \
        : "+f"((c)[0]), "+f"((c)[1]), "+f"((c)[2]), "+f"((c)[3]) \
        : "r"((a)[0]), "r"((a)[1]), "r"((a)[2]), "r"((a)[3]), "r"((b)[0]), "r"((b)[1]))
#define CP16(dst, src) \
    asm volatile("cp.async.ca.shared.global [%0], [%1], 16;" :: "r"(dst), "l"(src) : "memory")
#define CP16Z(dst, src, n) \
    asm volatile("cp.async.ca.shared.global [%0], [%1], 16, %2;" :: "r"(dst), "l"(src), "r"(n) : "memory")
#define CP_COMMIT() asm volatile("cp.async.commit_group;" ::: "memory")
#define CP_WAIT2()  asm volatile("cp.async.wait_group 2;" ::: "memory")

// ---------------- K0: per-launch reset ----------------
__global__ void k_init() {
    int i = blockIdx.x * blockDim.x + threadIdx.x;
    if (i < E_EXP * C_CAP) {
        g_src[i] = -1;
        g_rowsum[i] = 0.f;
    }
}

// ---------------- K1: gating (exact fp32 routing) + x->fp16 conversion ----------------
__global__ void k_gate(const float* __restrict__ x, const float* __restrict__ Wg) {
    int warp = threadIdx.x >> 5;
    int lane = threadIdx.x & 31;
    int tok = blockIdx.x * 8 + warp;
    if (tok >= T_TOK) return;
    const float* xr = x + (size_t)tok * D_DIM;
    __half* xhw = g_xh + (size_t)tok * D_DIM;

    float acc[8];
#pragma unroll
    for (int e = 0; e < 8; e++) acc[e] = 0.f;
    for (int k4 = lane; k4 < D_DIM / 4; k4 += 32) {
        const int k = k4 * 4;
        float4 xv = *(const float4*)(xr + k);
        // fused fp16 conversion (coalesced 8B/lane)
        *(__half2*)(xhw + k)     = __floats2half2_rn(xv.x, xv.y);
        *(__half2*)(xhw + k + 2) = __floats2half2_rn(xv.z, xv.w);
        const float xs[4] = {xv.x, xv.y, xv.z, xv.w};
#pragma unroll
        for (int j = 0; j < 4; j++) {
            const float* wr = Wg + (size_t)(k + j) * 8;
            float4 w0 = *(const float4*)(wr);
            float4 w1 = *(const float4*)(wr + 4);
            acc[0] = fmaf(xs[j], w0.x, acc[0]);
            acc[1] = fmaf(xs[j], w0.y, acc[1]);
            acc[2] = fmaf(xs[j], w0.z, acc[2]);
            acc[3] = fmaf(xs[j], w0.w, acc[3]);
            acc[4] = fmaf(xs[j], w1.x, acc[4]);
            acc[5] = fmaf(xs[j], w1.y, acc[5]);
            acc[6] = fmaf(xs[j], w1.z, acc[6]);
            acc[7] = fmaf(xs[j], w1.w, acc[7]);
        }
    }
#pragma unroll
    for (int e = 0; e < 8; e++) {
#pragma unroll
        for (int off = 16; off > 0; off >>= 1)
            acc[e] += __shfl_xor_sync(0xffffffffu, acc[e], off);
    }
    if (lane == 0) {
        float l0 = acc[0]; int i0 = 0;
#pragma unroll
        for (int e = 1; e < 8; e++) if (acc[e] > l0) { l0 = acc[e]; i0 = e; }
        float l1 = -INFINITY; int i1 = 0;
#pragma unroll
        for (int e = 0; e < 8; e++) if (e != i0 && acc[e] > l1) { l1 = acc[e]; i1 = e; }
        float g0 = 1.f / (1.f + __expf(l1 - l0));
        g_e0[tok] = i0; g_e1[tok] = i1;
        g_g0[tok] = g0; g_g1[tok] = 1.f - g0;
    }
}

// ---------------- K2: dispatch scan (single block, shfl-based) ----------------
__global__ void k_scan() {
    __shared__ int warpOff[8][8];
    __shared__ int shTot[8];
    const int tid = threadIdx.x, lane = tid & 31, w = tid >> 5;
    const int base = tid * 32;

    int cnt[8];
#pragma unroll
    for (int e = 0; e < 8; e++) cnt[e] = 0;
    for (int i = 0; i < 32; i++) cnt[g_e0[base + i]]++;
    int inc[8];
#pragma unroll
    for (int e = 0; e < 8; e++) inc[e] = cnt[e];
#pragma unroll
    for (int off = 1; off < 32; off <<= 1) {
#pragma unroll
        for (int e = 0; e < 8; e++) {
            int v = __shfl_up_sync(0xffffffffu, inc[e], off);
            if (lane >= off) inc[e] += v;
        }
    }
    if (lane == 31) {
#pragma unroll
        for (int e = 0; e < 8; e++) warpOff[w][e] = inc[e];
    }
    __syncthreads();
    if (w == 0 && lane < 8) {
        int s = 0;
        for (int ww = 0; ww < 8; ww++) {
            int t = warpOff[ww][lane];
            warpOff[ww][lane] = s;
            s += t;
        }
        shTot[lane] = s;
    }
    __syncthreads();
    int run[8];
#pragma unroll
    for (int e = 0; e < 8; e++) run[e] = warpOff[w][e] + inc[e] - cnt[e];
    for (int i = 0; i < 32; i++) {
        int tok = base + i;
        int e = g_e0[tok];
        int pos = run[e]++;
        if (pos < C_CAP) { g_p0[tok] = pos; g_src[e * C_CAP + pos] = tok; }
        else             { g_p0[tok] = -1; }
    }
    __syncthreads();

#pragma unroll
    for (int e = 0; e < 8; e++) cnt[e] = 0;
    for (int i = 0; i < 32; i++) cnt[g_e1[base + i]]++;
#pragma unroll
    for (int e = 0; e < 8; e++) inc[e] = cnt[e];
#pragma unroll
    for (int off = 1; off < 32; off <<= 1) {
#pragma unroll
        for (int e = 0; e < 8; e++) {
            int v = __shfl_up_sync(0xffffffffu, inc[e], off);
            if (lane >= off) inc[e] += v;
        }
    }
    if (lane == 31) {
#pragma unroll
        for (int e = 0; e < 8; e++) warpOff[w][e] = inc[e];
    }
    __syncthreads();
    if (w == 0 && lane < 8) {
        int s = 0;
        for (int ww = 0; ww < 8; ww++) {
            int t = warpOff[ww][lane];
            warpOff[ww][lane] = s;
            s += t;
        }
    }
    __syncthreads();
#pragma unroll
    for (int e = 0; e < 8; e++) run[e] = shTot[e] + warpOff[w][e] + inc[e] - cnt[e];
    for (int i = 0; i < 32; i++) {
        int tok = base + i;
        int e = g_e1[tok];
        int pos = run[e]++;
        if (pos < C_CAP) { g_p1[tok] = pos; g_src[e * C_CAP + pos] = tok; }
        else             { g_p1[tok] = -1; }
    }
}

// ---------------- K3a: w2sum ----------------
__global__ void k_w2sum(const float* __restrict__ W2) {
    int gw = (blockIdx.x * blockDim.x + threadIdx.x) >> 5;
    int lane = threadIdx.x & 31;
    if (gw >= E_EXP * H_DIM) return;
    const float* r = W2 + (size_t)gw * D_DIM;
    float s = 0.f;
    for (int k = lane * 4; k < D_DIM; k += 128) {
        float4 v = *(const float4*)(r + k);
        s += (v.x + v.y) + (v.z + v.w);
    }
#pragma unroll
    for (int off = 16; off > 0; off >>= 1) s += __shfl_xor_sync(0xffffffffu, s, off);
    if (lane == 0) g_w2sum[gw] = s;
}

// ---------------- K3b: b2sum ----------------
__global__ void k_b2sum(const float* __restrict__ b2) {
    int w = threadIdx.x >> 5, lane = threadIdx.x & 31;
    if (w >= E_EXP) return;
    float s = 0.f;
    for (int k = lane; k < D_DIM; k += 32) s += b2[(size_t)w * D_DIM + k];
#pragma unroll
    for (int off = 16; off > 0; off >>= 1) s += __shfl_xor_sync(0xffffffffu, s, off);
    if (lane == 0) g_b2sum[w] = s;
}

// ---------------- K3c: transpose W1 -> [E][H][D] fp16 ----------------
__global__ void k_w1t(const float* __restrict__ W1) {
    __shared__ float tl[32][33];
    int e = blockIdx.z;
    int h0 = blockIdx.x * 32, d0 = blockIdx.y * 32;
    int tx = threadIdx.x, ty = threadIdx.y;
#pragma unroll
    for (int i = 0; i < 4; i++) {
        int d = d0 + ty + i * 8;
        tl[ty + i * 8][tx] = W1[((size_t)e * D_DIM + d) * H_DIM + h0 + tx];
    }
    __syncthreads();
#pragma unroll
    for (int i = 0; i < 4; i++) {
        int h = h0 + ty + i * 8;
        size_t o = ((size_t)e * H_DIM + h) * D_DIM + d0 + tx;
        g_w1h[o] = __float2half_rn(tl[tx][ty + i * 8]);
    }
}

// ---------------- K4: HMMA fused expert GEMM + relu*w2sum epilogue ----------------
// Tile M=128 x N=256, BK=32, 8 warps (2 wm x 4 wn, warp tile 64x64), single fp16 pass.
// 4-stage cp.async pipeline, padded 80B row stride.
#define STRIDE 80
#define OFF_A  0                              // 128 rows * 80 = 10240
#define OFF_B  10240                          // 256 rows * 80 = 20480
#define STAGE_SZ 30720
#define NSTAGE 4
#define OFF_W2 (STAGE_SZ * NSTAGE)            // 122880
#define OFF_B1 (OFF_W2 + 1024)
#define SMEM_FFN (OFF_B1 + 1024)              // 124928
#define NIT (D_DIM / 32)                      // 64

__global__ void __launch_bounds__(256, 1) k_ffn(const float* __restrict__ b1) {
    extern __shared__ char smem[];
    const uint32_t sbase = smem_u32(smem);
    const int tid = threadIdx.x;
    const int lane = tid & 31, wid = tid >> 5;
    const int wm = wid >> 2, wn = wid & 3;
    const int e = blockIdx.z;
    const int row0 = blockIdx.y * 128;
    const int col0 = blockIdx.x * 256;

    float* sW2 = (float*)(smem + OFF_W2);
    float* sB1 = (float*)(smem + OFF_B1);
    sW2[tid] = g_w2sum[e * H_DIM + col0 + tid];
    sB1[tid] = b1[(size_t)e * H_DIM + col0 + tid];

    // ---- loader assignment ----
    // A: 2 threads per row (128 rows), 32B each
    const int alr = tid >> 1;
    const int akseg = tid & 1;
    const int srcTok = g_src[e * C_CAP + row0 + alr];
    const int aPred = (srcTok >= 0) ? 16 : 0;
    const __half* aPtr = g_xh + (size_t)(srcTok >= 0 ? srcTok : 0) * D_DIM + akseg * 16;
    const int aByte = alr * STRIDE + akseg * 32;
    // B: 512 slots (256 rows x 2), thread handles slots tid and tid+256
    const int br0 = tid >> 1,            bk0 = tid & 1;
    const int br1 = (tid + 256) >> 1,    bk1 = tid & 1;  // (tid+256)&1 == tid&1
    const __half* bPtr0 = g_w1h + (size_t)(e * H_DIM + col0 + br0) * D_DIM + bk0 * 16;
    const __half* bPtr1 = g_w1h + (size_t)(e * H_DIM + col0 + br1) * D_DIM + bk1 * 16;
    const int bByte0 = br0 * STRIDE + bk0 * 32;
    const int bByte1 = br1 * STRIDE + bk1 * 32;

    float acc[4][8][4];
#pragma unroll
    for (int i = 0; i < 4; i++)
#pragma unroll
        for (int j = 0; j < 8; j++)
#pragma unroll
            for (int q = 0; q < 4; q++) acc[i][j][q] = 0.f;

    auto issue = [&](int it, int st) {
        const uint32_t sb = sbase + st * STAGE_SZ;
        const int co = it * 32;
        CP16Z(sb + OFF_A + aByte,      aPtr + co,     aPred);
        CP16Z(sb + OFF_A + aByte + 16, aPtr + co + 8, aPred);
        CP16(sb + OFF_B + bByte0,      bPtr0 + co);
        CP16(sb + OFF_B + bByte0 + 16, bPtr0 + co + 8);
        CP16(sb + OFF_B + bByte1,      bPtr1 + co);
        CP16(sb + OFF_B + bByte1 + 16, bPtr1 + co + 8);
    };

    issue(0, 0); CP_COMMIT();
    issue(1, 1); CP_COMMIT();
    issue(2, 2); CP_COMMIT();

    const uint32_t aFragOff = (wm * 64 + (lane & 15)) * STRIDE + ((lane >> 4) << 4);
    const uint32_t bFragOff = (wn * 64 + (lane & 15)) * STRIDE + ((lane >> 4) << 4);

    for (int it = 0; it < NIT; it++) {
        const int st = it & (NSTAGE - 1);
        CP_WAIT2();
        __syncthreads();
        if (it + 3 < NIT) issue(it + 3, (it + 3) & (NSTAGE - 1));
        CP_COMMIT();

        const uint32_t aB = sbase + st * STAGE_SZ + OFF_A + aFragOff;
        const uint32_t bB = sbase + st * STAGE_SZ + OFF_B + bFragOff;
#pragma unroll
        for (int kh = 0; kh < 2; kh++) {
            uint32_t a[4][4], b[8][2];
#pragma unroll
            for (int ma = 0; ma < 4; ma++)
                LDM4(a[ma], aB + ma * (16 * STRIDE) + kh * 32);
#pragma unroll
            for (int np = 0; np < 4; np++) {
                uint32_t tr[4];
                LDM4(tr, bB + np * (16 * STRIDE) + kh * 32);
                b[np * 2][0] = tr[0];     b[np * 2][1] = tr[2];
                b[np * 2 + 1][0] = tr[1]; b[np * 2 + 1][1] = tr[3];
            }
#pragma unroll
            for (int ma = 0; ma < 4; ma++)
#pragma unroll
                for (int na = 0; na < 8; na++)
                    MMA(acc[ma][na], a[ma], b[na]);
        }
    }

    // ---- epilogue: relu(z + b1) * w2sum, reduce over N, one atomic per row ----
#pragma unroll
    for (int ma = 0; ma < 4; ma++) {
        float s0 = 0.f, s1 = 0.f;
#pragma unroll
        for (int na = 0; na < 8; na++) {
            int cb = wn * 64 + na * 8 + (lane & 3) * 2;
            float w0 = sW2[cb], w1v = sW2[cb + 1];
            float bb0 = sB1[cb], bb1 = sB1[cb + 1];
            s0 += fmaxf(acc[ma][na][0] + bb0, 0.f) * w0
                + fmaxf(acc[ma][na][1] + bb1, 0.f) * w1v;
            s1 += fmaxf(acc[ma][na][2] + bb0, 0.f) * w0
                + fmaxf(acc[ma][na][3] + bb1, 0.f) * w1v;
        }
        s0 += __shfl_xor_sync(0xffffffffu, s0, 1);
        s0 += __shfl_xor_sync(0xffffffffu, s0, 2);
        s1 += __shfl_xor_sync(0xffffffffu, s1, 1);
        s1 += __shfl_xor_sync(0xffffffffu, s1, 2);
        if ((lane & 3) == 0) {
            int r = row0 + wm * 64 + ma * 16 + (lane >> 2);
            atomicAdd(&g_rowsum[e * C_CAP + r], s0);
            atomicAdd(&g_rowsum[e * C_CAP + r + 8], s1);
        }
    }
}

// ---------------- K5: combine ----------------
__global__ void k_combine() {
    int t = blockIdx.x * blockDim.x + threadIdx.x;
    if (t >= T_TOK) return;
    float y = 0.f;
    int p0 = g_p0[t];
    if (p0 >= 0) {
        int e = g_e0[t];
        y += g_g0[t] * (g_rowsum[e * C_CAP + p0] + g_b2sum[e]);
    }
    int p1 = g_p1[t];
    if (p1 >= 0) {
        int e = g_e1[t];
        y += g_g1[t] * (g_rowsum[e * C_CAP + p1] + g_b2sum[e]);
    }
    g_y[t] = y;
}

// ---------------- K6: log_softmax over S per batch ----------------
__global__ void k_lsm(float* __restrict__ out) {
    __shared__ float red[256];
    int b = blockIdx.x, tid = threadIdx.x;
    const float* yr = g_y + (size_t)b * S_SEQ;

    float m = -INFINITY;
    for (int s = tid; s < S_SEQ; s += 256) m = fmaxf(m, yr[s]);
    red[tid] = m; __syncthreads();
    for (int off = 128; off > 0; off >>= 1) {
        if (tid < off) red[tid] = fmaxf(red[tid], red[tid + off]);
        __syncthreads();
    }
    m = red[0]; __syncthreads();

    float sum = 0.f;
    for (int s = tid; s < S_SEQ; s += 256) sum += expf(yr[s] - m);
    red[tid] = sum; __syncthreads();
    for (int off = 128; off > 0; off >>= 1) {
        if (tid < off) red[tid] += red[tid + off];
        __syncthreads();
    }
    float lse = m + logf(red[0]);

    for (int s = tid; s < S_SEQ; s += 256)
        out[(size_t)b * S_SEQ + s] = yr[s] - lse;
}

// ---------------- launch ----------------
extern "C" void kernel_launch(void* const* d_in, const int* in_sizes, int n_in,
                              void* d_out, int out_size) {
    const float* x  = (const float*)d_in[0];
    const float* Wg = (const float*)d_in[1];
    const float* W1 = (const float*)d_in[2];
    const float* b1 = (const float*)d_in[3];
    const float* W2 = (const float*)d_in[4];
    const float* b2 = (const float*)d_in[5];
    float* out = (float*)d_out;

    cudaFuncSetAttribute(k_ffn, cudaFuncAttributeMaxDynamicSharedMemorySize, SMEM_FFN);

    k_init<<<(E_EXP * C_CAP + 255) / 256, 256>>>();
    k_w1t<<<dim3(H_DIM / 32, D_DIM / 32, E_EXP), dim3(32, 8)>>>(W1);
    k_gate<<<T_TOK / 8, 256>>>(x, Wg);
    k_scan<<<1, 256>>>();
    k_w2sum<<<(E_EXP * H_DIM) / 8, 256>>>(W2);
    k_b2sum<<<1, 256>>>(b2);
    k_ffn<<<dim3(H_DIM / 256, C_CAP / 128, E_EXP), 256, SMEM_FFN>>>(b1);
    k_combine<<<T_TOK / 256, 256>>>();
    k_lsm<<<B_BATCH, 256>>>(out);
}

// round 7
// speedup vs baseline: 4.5434x; 1.0335x over previous
#include <cuda_runtime.h>
#include <cuda_fp16.h>
#include <math.h>
#include <stdint.h>

// Problem dims (fixed by setup_inputs)
#define T_TOK 8192
#define D_DIM 2048
#define E_EXP 8
#define H_DIM 2048
#define C_CAP 2048
#define B_BATCH 4
#define S_SEQ 2048

// ---------------- device scratch (allocation-free) ----------------
__device__ int   g_e0[T_TOK], g_e1[T_TOK];
__device__ float g_g0[T_TOK], g_g1[T_TOK];
__device__ int   g_p0[T_TOK], g_p1[T_TOK];
__device__ int   g_src[E_EXP * C_CAP];
__device__ float g_w2sum[E_EXP * H_DIM];
__device__ float g_b2sum[E_EXP];
__device__ float g_rowsum[E_EXP * C_CAP];
// fp16 copies: x (written by prep/gate), W1 transposed [e][h][d]
__device__ __align__(16) __half g_xh[(size_t)T_TOK * D_DIM];
__device__ __align__(16) __half g_w1h[(size_t)E_EXP * H_DIM * D_DIM];

// ---------------- helpers ----------------
__device__ __forceinline__ uint32_t smem_u32(const void* p) {
    uint32_t a;
    asm("{ .reg .u64 t; cvta.to.shared.u64 t, %1; cvt.u32.u64 %0, t; }" : "=r"(a) : "l"(p));
    return a;
}
#define LDM4(d, a) \
    asm volatile("ldmatrix.sync.aligned.m8n8.x4.shared.b16 {%0,%1,%2,%3}, [%4];" \
        : "=r"((d)[0]), "=r"((d)[1]), "=r"((d)[2]), "=r"((d)[3]) : "r"(a))
#define MMA(c, a, b) \
    asm volatile("mma.sync.aligned.m16n8k16.row.col.f32.f16.f16.f32 " \
        "{%0,%1,%2,%3},{%4,%5,%6,%7},{%8,%9},{%0,%1,%2,%3};" \
        : "+f"((c)[0]), "+f"((c)[1]), "+f"((c)[2]), "+f"((c)[3]) \
        : "r"((a)[0]), "r"((a)[1]), "r"((a)[2]), "r"((a)[3]), "r"((b)[0]), "r"((b)[1]))
#define CP16(dst, src) \
    asm volatile("cp.async.ca.shared.global [%0], [%1], 16;" :: "r"(dst), "l"(src) : "memory")
#define CP16Z(dst, src, n) \
    asm volatile("cp.async.ca.shared.global [%0], [%1], 16, %2;" :: "r"(dst), "l"(src), "r"(n) : "memory")
#define CP_COMMIT() asm volatile("cp.async.commit_group;" ::: "memory")
#define CP_WAIT2()  asm volatile("cp.async.wait_group 2;" ::: "memory")

// ================= K1: fused prep =================
// Interleaved block roles, period 35: [32 w1t | 1 gate | 2 w2sum] x 1024,
// then 64 init blocks + 1 b2sum block.
#define GB_PERIOD 35
#define G_MAIN (1024 * GB_PERIOD)      // 35840
#define G_INIT 64
#define G_PREP (G_MAIN + G_INIT + 1)   // 35905

__global__ void __launch_bounds__(256) k_prep(const float* __restrict__ x,
                                              const float* __restrict__ Wg,
                                              const float* __restrict__ W1,
                                              const float* __restrict__ W2,
                                              const float* __restrict__ b2) {
    __shared__ float tl[32][33];
    const int bid = blockIdx.x, tid = threadIdx.x;
    const int lane = tid & 31, wrp = tid >> 5;

    if (bid < G_MAIN) {
        const int p = bid / GB_PERIOD, r = bid % GB_PERIOD;
        if (r < 32) {
            // ---- w1t: transpose W1 -> [e][h][d] fp16, 32x32 tile ----
            const int w = p * 32 + r;
            const int e = w >> 12;
            const int rem = w & 4095;
            const int h0 = (rem >> 6) * 32, d0 = (rem & 63) * 32;
            const int tx = lane, ty = wrp;
#pragma unroll
            for (int i = 0; i < 4; i++) {
                int d = d0 + ty + i * 8;
                tl[ty + i * 8][tx] = W1[((size_t)e * D_DIM + d) * H_DIM + h0 + tx];
            }
            __syncthreads();
#pragma unroll
            for (int i = 0; i < 4; i++) {
                int h = h0 + ty + i * 8;
                g_w1h[((size_t)e * H_DIM + h) * D_DIM + d0 + tx] =
                    __float2half_rn(tl[tx][ty + i * 8]);
            }
        } else if (r == 32) {
            // ---- gate: exact fp32 routing + x->fp16, one warp per token ----
            const int tok = p * 8 + wrp;
            const float* xr = x + (size_t)tok * D_DIM;
            __half* xhw = g_xh + (size_t)tok * D_DIM;
            float acc[8];
#pragma unroll
            for (int e = 0; e < 8; e++) acc[e] = 0.f;
            for (int k4 = lane; k4 < D_DIM / 4; k4 += 32) {
                const int k = k4 * 4;
                float4 xv = *(const float4*)(xr + k);
                *(__half2*)(xhw + k)     = __floats2half2_rn(xv.x, xv.y);
                *(__half2*)(xhw + k + 2) = __floats2half2_rn(xv.z, xv.w);
                const float xs[4] = {xv.x, xv.y, xv.z, xv.w};
#pragma unroll
                for (int j = 0; j < 4; j++) {
                    const float* wr = Wg + (size_t)(k + j) * 8;
                    float4 w0 = *(const float4*)(wr);
                    float4 w1v = *(const float4*)(wr + 4);
                    acc[0] = fmaf(xs[j], w0.x, acc[0]);
                    acc[1] = fmaf(xs[j], w0.y, acc[1]);
                    acc[2] = fmaf(xs[j], w0.z, acc[2]);
                    acc[3] = fmaf(xs[j], w0.w, acc[3]);
                    acc[4] = fmaf(xs[j], w1v.x, acc[4]);
                    acc[5] = fmaf(xs[j], w1v.y, acc[5]);
                    acc[6] = fmaf(xs[j], w1v.z, acc[6]);
                    acc[7] = fmaf(xs[j], w1v.w, acc[7]);
                }
            }
#pragma unroll
            for (int e = 0; e < 8; e++) {
#pragma unroll
                for (int off = 16; off > 0; off >>= 1)
                    acc[e] += __shfl_xor_sync(0xffffffffu, acc[e], off);
            }
            if (lane == 0) {
                float l0 = acc[0]; int i0 = 0;
#pragma unroll
                for (int e = 1; e < 8; e++) if (acc[e] > l0) { l0 = acc[e]; i0 = e; }
                float l1 = -INFINITY; int i1 = 0;
#pragma unroll
                for (int e = 0; e < 8; e++) if (e != i0 && acc[e] > l1) { l1 = acc[e]; i1 = e; }
                float g0 = 1.f / (1.f + __expf(l1 - l0));
                g_e0[tok] = i0; g_e1[tok] = i1;
                g_g0[tok] = g0; g_g1[tok] = 1.f - g0;
            }
        } else {
            // ---- w2sum: one warp per (e,h) row ----
            const int v = p * 2 + (r - 33);
            const int gw = v * 8 + wrp;          // < 16384
            const float* rr = W2 + (size_t)gw * D_DIM;
            float s = 0.f;
            for (int k = lane * 4; k < D_DIM; k += 128) {
                float4 vv = *(const float4*)(rr + k);
                s += (vv.x + vv.y) + (vv.z + vv.w);
            }
#pragma unroll
            for (int off = 16; off > 0; off >>= 1) s += __shfl_xor_sync(0xffffffffu, s, off);
            if (lane == 0) g_w2sum[gw] = s;
        }
    } else if (bid < G_MAIN + G_INIT) {
        // ---- init: reset src/rowsum ----
        int i = (bid - G_MAIN) * 256 + tid;
        g_src[i] = -1;
        g_rowsum[i] = 0.f;
    } else {
        // ---- b2sum ----
        if (wrp < 8) {
            float s = 0.f;
            for (int k = lane; k < D_DIM; k += 32) s += b2[(size_t)wrp * D_DIM + k];
#pragma unroll
            for (int off = 16; off > 0; off >>= 1) s += __shfl_xor_sync(0xffffffffu, s, off);
            if (lane == 0) g_b2sum[wrp] = s;
        }
    }
}

// ================= K2: dispatch scan (1024 threads, both choices in one pass) =================
__global__ void __launch_bounds__(1024) k_scan() {
    __shared__ int wT0[32][8], wT1[32][8];
    __shared__ int wOff0[32][8], wOff1[32][8];
    __shared__ int shTot[8];
    const int tid = threadIdx.x, lane = tid & 31, w = tid >> 5;
    const int base = tid * 8;

    int4 a0 = *(const int4*)&g_e0[base];
    int4 a1 = *(const int4*)&g_e0[base + 4];
    int4 c0 = *(const int4*)&g_e1[base];
    int4 c1 = *(const int4*)&g_e1[base + 4];
    const int e0s[8] = {a0.x, a0.y, a0.z, a0.w, a1.x, a1.y, a1.z, a1.w};
    const int e1s[8] = {c0.x, c0.y, c0.z, c0.w, c1.x, c1.y, c1.z, c1.w};

    int cnt0[8], cnt1[8];
#pragma unroll
    for (int e = 0; e < 8; e++) { cnt0[e] = 0; cnt1[e] = 0; }
#pragma unroll
    for (int i = 0; i < 8; i++) { cnt0[e0s[i]]++; cnt1[e1s[i]]++; }

    int inc0[8], inc1[8];
#pragma unroll
    for (int e = 0; e < 8; e++) { inc0[e] = cnt0[e]; inc1[e] = cnt1[e]; }
#pragma unroll
    for (int off = 1; off < 32; off <<= 1) {
#pragma unroll
        for (int e = 0; e < 8; e++) {
            int v0 = __shfl_up_sync(0xffffffffu, inc0[e], off);
            int v1 = __shfl_up_sync(0xffffffffu, inc1[e], off);
            if (lane >= off) { inc0[e] += v0; inc1[e] += v1; }
        }
    }
    if (lane == 31) {
#pragma unroll
        for (int e = 0; e < 8; e++) { wT0[w][e] = inc0[e]; wT1[w][e] = inc1[e]; }
    }
    __syncthreads();
    if (w == 0) {
        int t0[8], t1[8], i0[8], i1[8];
#pragma unroll
        for (int e = 0; e < 8; e++) {
            t0[e] = wT0[lane][e]; t1[e] = wT1[lane][e];
            i0[e] = t0[e]; i1[e] = t1[e];
        }
#pragma unroll
        for (int off = 1; off < 32; off <<= 1) {
#pragma unroll
            for (int e = 0; e < 8; e++) {
                int v0 = __shfl_up_sync(0xffffffffu, i0[e], off);
                int v1 = __shfl_up_sync(0xffffffffu, i1[e], off);
                if (lane >= off) { i0[e] += v0; i1[e] += v1; }
            }
        }
#pragma unroll
        for (int e = 0; e < 8; e++) {
            wOff0[lane][e] = i0[e] - t0[e];
            wOff1[lane][e] = i1[e] - t1[e];
        }
        if (lane == 31) {
#pragma unroll
            for (int e = 0; e < 8; e++) shTot[e] = i0[e];   // total choice-0 count
        }
    }
    __syncthreads();

    int run0[8], run1[8];
#pragma unroll
    for (int e = 0; e < 8; e++) {
        run0[e] = wOff0[w][e] + inc0[e] - cnt0[e];
        run1[e] = shTot[e] + wOff1[w][e] + inc1[e] - cnt1[e];
    }
#pragma unroll
    for (int i = 0; i < 8; i++) {
        int tok = base + i;
        int e = e0s[i];
        int pos = run0[e]++;
        if (pos < C_CAP) { g_p0[tok] = pos; g_src[e * C_CAP + pos] = tok; }
        else             { g_p0[tok] = -1; }
    }
#pragma unroll
    for (int i = 0; i < 8; i++) {
        int tok = base + i;
        int e = e1s[i];
        int pos = run1[e]++;
        if (pos < C_CAP) { g_p1[tok] = pos; g_src[e * C_CAP + pos] = tok; }
        else             { g_p1[tok] = -1; }
    }
}

// ================= K3: HMMA fused expert GEMM + relu*w2sum epilogue =================
// Tile M=128 x N=256, BK=32, 8 warps (2 wm x 4 wn, warp tile 64x64), single fp16 pass.
#define STRIDE 80
#define OFF_A  0
#define OFF_B  10240
#define STAGE_SZ 30720
#define NSTAGE 4
#define OFF_W2 (STAGE_SZ * NSTAGE)
#define OFF_B1 (OFF_W2 + 1024)
#define SMEM_FFN (OFF_B1 + 1024)
#define NIT (D_DIM / 32)

__global__ void __launch_bounds__(256, 1) k_ffn(const float* __restrict__ b1) {
    extern __shared__ char smem[];
    const uint32_t sbase = smem_u32(smem);
    const int tid = threadIdx.x;
    const int lane = tid & 31, wid = tid >> 5;
    const int wm = wid >> 2, wn = wid & 3;
    const int e = blockIdx.z;
    const int row0 = blockIdx.y * 128;
    const int col0 = blockIdx.x * 256;

    float* sW2 = (float*)(smem + OFF_W2);
    float* sB1 = (float*)(smem + OFF_B1);
    sW2[tid] = g_w2sum[e * H_DIM + col0 + tid];
    sB1[tid] = b1[(size_t)e * H_DIM + col0 + tid];

    const int alr = tid >> 1;
    const int akseg = tid & 1;
    const int srcTok = g_src[e * C_CAP + row0 + alr];
    const int aPred = (srcTok >= 0) ? 16 : 0;
    const __half* aPtr = g_xh + (size_t)(srcTok >= 0 ? srcTok : 0) * D_DIM + akseg * 16;
    const int aByte = alr * STRIDE + akseg * 32;
    const int br0 = tid >> 1,         bk0 = tid & 1;
    const int br1 = (tid + 256) >> 1, bk1 = tid & 1;
    const __half* bPtr0 = g_w1h + (size_t)(e * H_DIM + col0 + br0) * D_DIM + bk0 * 16;
    const __half* bPtr1 = g_w1h + (size_t)(e * H_DIM + col0 + br1) * D_DIM + bk1 * 16;
    const int bByte0 = br0 * STRIDE + bk0 * 32;
    const int bByte1 = br1 * STRIDE + bk1 * 32;

    float acc[4][8][4];
#pragma unroll
    for (int i = 0; i < 4; i++)
#pragma unroll
        for (int j = 0; j < 8; j++)
#pragma unroll
            for (int q = 0; q < 4; q++) acc[i][j][q] = 0.f;

    auto issue = [&](int it, int st) {
        const uint32_t sb = sbase + st * STAGE_SZ;
        const int co = it * 32;
        CP16Z(sb + OFF_A + aByte,      aPtr + co,     aPred);
        CP16Z(sb + OFF_A + aByte + 16, aPtr + co + 8, aPred);
        CP16(sb + OFF_B + bByte0,      bPtr0 + co);
        CP16(sb + OFF_B + bByte0 + 16, bPtr0 + co + 8);
        CP16(sb + OFF_B + bByte1,      bPtr1 + co);
        CP16(sb + OFF_B + bByte1 + 16, bPtr1 + co + 8);
    };

    issue(0, 0); CP_COMMIT();
    issue(1, 1); CP_COMMIT();
    issue(2, 2); CP_COMMIT();

    const uint32_t aFragOff = (wm * 64 + (lane & 15)) * STRIDE + ((lane >> 4) << 4);
    const uint32_t bFragOff = (wn * 64 + (lane & 15)) * STRIDE + ((lane >> 4) << 4);

    for (int it = 0; it < NIT; it++) {
        const int st = it & (NSTAGE - 1);
        CP_WAIT2();
        __syncthreads();
        if (it + 3 < NIT) issue(it + 3, (it + 3) & (NSTAGE - 1));
        CP_COMMIT();

        const uint32_t aB = sbase + st * STAGE_SZ + OFF_A + aFragOff;
        const uint32_t bB = sbase + st * STAGE_SZ + OFF_B + bFragOff;
#pragma unroll
        for (int kh = 0; kh < 2; kh++) {
            uint32_t a[4][4], b[8][2];
#pragma unroll
            for (int ma = 0; ma < 4; ma++)
                LDM4(a[ma], aB + ma * (16 * STRIDE) + kh * 32);
#pragma unroll
            for (int np = 0; np < 4; np++) {
                uint32_t tr[4];
                LDM4(tr, bB + np * (16 * STRIDE) + kh * 32);
                b[np * 2][0] = tr[0];     b[np * 2][1] = tr[2];
                b[np * 2 + 1][0] = tr[1]; b[np * 2 + 1][1] = tr[3];
            }
#pragma unroll
            for (int ma = 0; ma < 4; ma++)
#pragma unroll
                for (int na = 0; na < 8; na++)
                    MMA(acc[ma][na], a[ma], b[na]);
        }
    }

#pragma unroll
    for (int ma = 0; ma < 4; ma++) {
        float s0 = 0.f, s1 = 0.f;
#pragma unroll
        for (int na = 0; na < 8; na++) {
            int cb = wn * 64 + na * 8 + (lane & 3) * 2;
            float w0 = sW2[cb], w1v = sW2[cb + 1];
            float bb0 = sB1[cb], bb1 = sB1[cb + 1];
            s0 += fmaxf(acc[ma][na][0] + bb0, 0.f) * w0
                + fmaxf(acc[ma][na][1] + bb1, 0.f) * w1v;
            s1 += fmaxf(acc[ma][na][2] + bb0, 0.f) * w0
                + fmaxf(acc[ma][na][3] + bb1, 0.f) * w1v;
        }
        s0 += __shfl_xor_sync(0xffffffffu, s0, 1);
        s0 += __shfl_xor_sync(0xffffffffu, s0, 2);
        s1 += __shfl_xor_sync(0xffffffffu, s1, 1);
        s1 += __shfl_xor_sync(0xffffffffu, s1, 2);
        if ((lane & 3) == 0) {
            int r = row0 + wm * 64 + ma * 16 + (lane >> 2);
            atomicAdd(&g_rowsum[e * C_CAP + r], s0);
            atomicAdd(&g_rowsum[e * C_CAP + r + 8], s1);
        }
    }
}

// ================= K4: fused combine + log_softmax =================
__global__ void __launch_bounds__(256) k_out(float* __restrict__ out) {
    __shared__ float sy[S_SEQ];
    __shared__ float red[256];
    const int b = blockIdx.x, tid = threadIdx.x;

    for (int s = tid; s < S_SEQ; s += 256) {
        int t = b * S_SEQ + s;
        float y = 0.f;
        int p0 = g_p0[t];
        if (p0 >= 0) {
            int e = g_e0[t];
            y += g_g0[t] * (g_rowsum[e * C_CAP + p0] + g_b2sum[e]);
        }
        int p1 = g_p1[t];
        if (p1 >= 0) {
            int e = g_e1[t];
            y += g_g1[t] * (g_rowsum[e * C_CAP + p1] + g_b2sum[e]);
        }
        sy[s] = y;
    }
    __syncthreads();

    float m = -INFINITY;
    for (int s = tid; s < S_SEQ; s += 256) m = fmaxf(m, sy[s]);
    red[tid] = m; __syncthreads();
    for (int off = 128; off > 0; off >>= 1) {
        if (tid < off) red[tid] = fmaxf(red[tid], red[tid + off]);
        __syncthreads();
    }
    m = red[0]; __syncthreads();

    float sum = 0.f;
    for (int s = tid; s < S_SEQ; s += 256) sum += expf(sy[s] - m);
    red[tid] = sum; __syncthreads();
    for (int off = 128; off > 0; off >>= 1) {
        if (tid < off) red[tid] += red[tid + off];
        __syncthreads();
    }
    float lse = m + logf(red[0]);

    for (int s = tid; s < S_SEQ; s += 256)
        out[(size_t)b * S_SEQ + s] = sy[s] - lse;
}

// ---------------- launch ----------------
extern "C" void kernel_launch(void* const* d_in, const int* in_sizes, int n_in,
                              void* d_out, int out_size) {
    const float* x  = (const float*)d_in[0];
    const float* Wg = (const float*)d_in[1];
    const float* W1 = (const float*)d_in[2];
    const float* b1 = (const float*)d_in[3];
    const float* W2 = (const float*)d_in[4];
    const float* b2 = (const float*)d_in[5];
    float* out = (float*)d_out;

    cudaFuncSetAttribute(k_ffn, cudaFuncAttributeMaxDynamicSharedMemorySize, SMEM_FFN);

    k_prep<<<G_PREP, 256>>>(x, Wg, W1, W2, b2);
    k_scan<<<1, 1024>>>();
    k_ffn<<<dim3(H_DIM / 256, C_CAP / 128, E_EXP), 256, SMEM_FFN>>>(b1);
    k_out<<<B_BATCH, 256>>>(out);
}

// round 10
// speedup vs baseline: 4.6770x; 1.0294x over previous
#include <cuda_runtime.h>
#include <cuda_fp16.h>
#include <math.h>
#include <stdint.h>

// Problem dims (fixed by setup_inputs)
#define T_TOK 8192
#define D_DIM 2048
#define E_EXP 8
#define H_DIM 2048
#define C_CAP 2048
#define B_BATCH 4
#define S_SEQ 2048

// ---------------- device scratch (allocation-free) ----------------
__device__ int   g_e0[T_TOK], g_e1[T_TOK];
__device__ float g_g0[T_TOK], g_g1[T_TOK];
__device__ int   g_p0[T_TOK], g_p1[T_TOK];
__device__ int   g_src[E_EXP * C_CAP];
__device__ float g_w2sum[E_EXP * H_DIM];
__device__ float g_b2sum[E_EXP];
__device__ float g_rowsum[E_EXP * C_CAP];
// fp16 copies: x (written by prep/gate), W1 transposed [e][h][d]
__device__ __align__(16) __half g_xh[(size_t)T_TOK * D_DIM];
__device__ __align__(16) __half g_w1h[(size_t)E_EXP * H_DIM * D_DIM];

// ---------------- helpers ----------------
__device__ __forceinline__ uint32_t smem_u32(const void* p) {
    uint32_t a;
    asm("{ .reg .u64 t; cvta.to.shared.u64 t, %1; cvt.u32.u64 %0, t; }" : "=r"(a) : "l"(p));
    return a;
}
#define LDM4(d, a) \
    asm volatile("ldmatrix.sync.aligned.m8n8.x4.shared.b16 {%0,%1,%2,%3}, [%4];" \
        : "=r"((d)[0]), "=r"((d)[1]), "=r"((d)[2]), "=r"((d)[3]) : "r"(a))
#define MMA(c, a, b) \
    asm volatile("mma.sync.aligned.m16n8k16.row.col.f32.f16.f16.f32 " \
        "{%0,%1,%2,%3},{%4,%5,%6,%7},{%8,%9},{%0,%1,%2,%3};" \
        : "+f"((c)[0]), "+f"((c)[1]), "+f"((c)[2]), "+f"((c)[3]) \
        : "r"((a)[0]), "r"((a)[1]), "r"((a)[2]), "r"((a)[3]), "r"((b)[0]), "r"((b)[1]))
#define CP16(dst, src) \
    asm volatile("cp.async.ca.shared.global [%0], [%1], 16;" :: "r"(dst), "l"(src) : "memory")
#define CP16Z(dst, src, n) \
    asm volatile("cp.async.ca.shared.global [%0], [%1], 16, %2;" :: "r"(dst), "l"(src), "r"(n) : "memory")
#define CP_COMMIT() asm volatile("cp.async.commit_group;" ::: "memory")
#define CP_WAIT2()  asm volatile("cp.async.wait_group 2;" ::: "memory")

// ================= K1: fused prep =================
// Interleaved roles, period 11: [8 w1t | 1 gate | 2 w2sum] x 1024,
// then 64 init blocks + 1 b2sum block.
// w1t: 8192 blocks (64x64 tiles), gate: 1024 blocks (8 tokens), w2sum: 2048 blocks (8 rows).
#define GB_PERIOD 11
#define G_MAIN (1024 * GB_PERIOD)      // 11264
#define G_INIT 64
#define G_PREP (G_MAIN + G_INIT + 1)

__global__ void __launch_bounds__(256) k_prep(const float* __restrict__ x,
                                              const float* __restrict__ Wg,
                                              const float* __restrict__ W1,
                                              const float* __restrict__ W2,
                                              const float* __restrict__ b2) {
    __shared__ float tl[64][65];
    const int bid = blockIdx.x, tid = threadIdx.x;
    const int lane = tid & 31, wrp = tid >> 5;

    if (bid < G_MAIN) {
        const int p = bid / GB_PERIOD, r = bid % GB_PERIOD;
        if (r < 8) {
            // ---- w1t: transpose W1 -> [e][h][d] fp16, 64x64 tile ----
            const int w = p * 8 + r;               // 0..8191
            const int e = w >> 10;                 // 1024 tiles per expert
            const int rem = w & 1023;
            const int h0 = (rem >> 5) * 64, d0 = (rem & 31) * 64;
            const int tx = tid & 63, ty = tid >> 6;   // 64 x 4
#pragma unroll
            for (int i = 0; i < 16; i++) {
                int dl = ty + i * 4;
                tl[dl][tx] = W1[((size_t)e * D_DIM + d0 + dl) * H_DIM + h0 + tx];
            }
            __syncthreads();
#pragma unroll
            for (int i = 0; i < 16; i++) {
                int hl = ty + i * 4;
                g_w1h[((size_t)e * H_DIM + h0 + hl) * D_DIM + d0 + tx] =
                    __float2half_rn(tl[tx][hl]);
            }
        } else if (r == 8) {
            // ---- gate: exact fp32 routing + x->fp16, one warp per token ----
            const int tok = p * 8 + wrp;
            const float* xr = x + (size_t)tok * D_DIM;
            __half* xhw = g_xh + (size_t)tok * D_DIM;
            float acc[8];
#pragma unroll
            for (int e = 0; e < 8; e++) acc[e] = 0.f;
            for (int k4 = lane; k4 < D_DIM / 4; k4 += 32) {
                const int k = k4 * 4;
                float4 xv = *(const float4*)(xr + k);
                *(__half2*)(xhw + k)     = __floats2half2_rn(xv.x, xv.y);
                *(__half2*)(xhw + k + 2) = __floats2half2_rn(xv.z, xv.w);
                const float xs[4] = {xv.x, xv.y, xv.z, xv.w};
#pragma unroll
                for (int j = 0; j < 4; j++) {
                    const float* wr = Wg + (size_t)(k + j) * 8;
                    float4 w0 = *(const float4*)(wr);
                    float4 w1v = *(const float4*)(wr + 4);
                    acc[0] = fmaf(xs[j], w0.x, acc[0]);
                    acc[1] = fmaf(xs[j], w0.y, acc[1]);
                    acc[2] = fmaf(xs[j], w0.z, acc[2]);
                    acc[3] = fmaf(xs[j], w0.w, acc[3]);
                    acc[4] = fmaf(xs[j], w1v.x, acc[4]);
                    acc[5] = fmaf(xs[j], w1v.y, acc[5]);
                    acc[6] = fmaf(xs[j], w1v.z, acc[6]);
                    acc[7] = fmaf(xs[j], w1v.w, acc[7]);
                }
            }
#pragma unroll
            for (int e = 0; e < 8; e++) {
#pragma unroll
                for (int off = 16; off > 0; off >>= 1)
                    acc[e] += __shfl_xor_sync(0xffffffffu, acc[e], off);
            }
            if (lane == 0) {
                float l0 = acc[0]; int i0 = 0;
#pragma unroll
                for (int e = 1; e < 8; e++) if (acc[e] > l0) { l0 = acc[e]; i0 = e; }
                float l1 = -INFINITY; int i1 = 0;
#pragma unroll
                for (int e = 0; e < 8; e++) if (e != i0 && acc[e] > l1) { l1 = acc[e]; i1 = e; }
                float g0 = 1.f / (1.f + __expf(l1 - l0));
                g_e0[tok] = i0; g_e1[tok] = i1;
                g_g0[tok] = g0; g_g1[tok] = 1.f - g0;
            }
        } else {
            // ---- w2sum: one warp per (e,h) row ----
            const int v = p * 2 + (r - 9);
            const int gw = v * 8 + wrp;            // < 16384
            const float* rr = W2 + (size_t)gw * D_DIM;
            float s = 0.f;
            for (int k = lane * 4; k < D_DIM; k += 128) {
                float4 vv = *(const float4*)(rr + k);
                s += (vv.x + vv.y) + (vv.z + vv.w);
            }
#pragma unroll
            for (int off = 16; off > 0; off >>= 1) s += __shfl_xor_sync(0xffffffffu, s, off);
            if (lane == 0) g_w2sum[gw] = s;
        }
    } else if (bid < G_MAIN + G_INIT) {
        int i = (bid - G_MAIN) * 256 + tid;
        g_src[i] = -1;
        g_rowsum[i] = 0.f;
    } else {
        if (wrp < 8) {
            float s = 0.f;
            for (int k = lane; k < D_DIM; k += 32) s += b2[(size_t)wrp * D_DIM + k];
#pragma unroll
            for (int off = 16; off > 0; off >>= 1) s += __shfl_xor_sync(0xffffffffu, s, off);
            if (lane == 0) g_b2sum[wrp] = s;
        }
    }
}

// ================= K2: dispatch scan (1024 threads, both choices in one pass) =================
__global__ void __launch_bounds__(1024) k_scan() {
    __shared__ int wT0[32][8], wT1[32][8];
    __shared__ int wOff0[32][8], wOff1[32][8];
    __shared__ int shTot[8];
    const int tid = threadIdx.x, lane = tid & 31, w = tid >> 5;
    const int base = tid * 8;

    int4 a0 = *(const int4*)&g_e0[base];
    int4 a1 = *(const int4*)&g_e0[base + 4];
    int4 c0 = *(const int4*)&g_e1[base];
    int4 c1 = *(const int4*)&g_e1[base + 4];
    const int e0s[8] = {a0.x, a0.y, a0.z, a0.w, a1.x, a1.y, a1.z, a1.w};
    const int e1s[8] = {c0.x, c0.y, c0.z, c0.w, c1.x, c1.y, c1.z, c1.w};

    int cnt0[8], cnt1[8];
#pragma unroll
    for (int e = 0; e < 8; e++) { cnt0[e] = 0; cnt1[e] = 0; }
#pragma unroll
    for (int i = 0; i < 8; i++) { cnt0[e0s[i]]++; cnt1[e1s[i]]++; }

    int inc0[8], inc1[8];
#pragma unroll
    for (int e = 0; e < 8; e++) { inc0[e] = cnt0[e]; inc1[e] = cnt1[e]; }
#pragma unroll
    for (int off = 1; off < 32; off <<= 1) {
#pragma unroll
        for (int e = 0; e < 8; e++) {
            int v0 = __shfl_up_sync(0xffffffffu, inc0[e], off);
            int v1 = __shfl_up_sync(0xffffffffu, inc1[e], off);
            if (lane >= off) { inc0[e] += v0; inc1[e] += v1; }
        }
    }
    if (lane == 31) {
#pragma unroll
        for (int e = 0; e < 8; e++) { wT0[w][e] = inc0[e]; wT1[w][e] = inc1[e]; }
    }
    __syncthreads();
    if (w == 0) {
        int t0[8], t1[8], i0[8], i1[8];
#pragma unroll
        for (int e = 0; e < 8; e++) {
            t0[e] = wT0[lane][e]; t1[e] = wT1[lane][e];
            i0[e] = t0[e]; i1[e] = t1[e];
        }
#pragma unroll
        for (int off = 1; off < 32; off <<= 1) {
#pragma unroll
            for (int e = 0; e < 8; e++) {
                int v0 = __shfl_up_sync(0xffffffffu, i0[e], off);
                int v1 = __shfl_up_sync(0xffffffffu, i1[e], off);
                if (lane >= off) { i0[e] += v0; i1[e] += v1; }
            }
        }
#pragma unroll
        for (int e = 0; e < 8; e++) {
            wOff0[lane][e] = i0[e] - t0[e];
            wOff1[lane][e] = i1[e] - t1[e];
        }
        if (lane == 31) {
#pragma unroll
            for (int e = 0; e < 8; e++) shTot[e] = i0[e];
        }
    }
    __syncthreads();

    int run0[8], run1[8];
#pragma unroll
    for (int e = 0; e < 8; e++) {
        run0[e] = wOff0[w][e] + inc0[e] - cnt0[e];
        run1[e] = shTot[e] + wOff1[w][e] + inc1[e] - cnt1[e];
    }
#pragma unroll
    for (int i = 0; i < 8; i++) {
        int tok = base + i;
        int e = e0s[i];
        int pos = run0[e]++;
        if (pos < C_CAP) { g_p0[tok] = pos; g_src[e * C_CAP + pos] = tok; }
        else             { g_p0[tok] = -1; }
    }
#pragma unroll
    for (int i = 0; i < 8; i++) {
        int tok = base + i;
        int e = e1s[i];
        int pos = run1[e]++;
        if (pos < C_CAP) { g_p1[tok] = pos; g_src[e * C_CAP + pos] = tok; }
        else             { g_p1[tok] = -1; }
    }
}

// ================= K3: HMMA fused expert GEMM + relu*w2sum epilogue (unchanged) =================
#define STRIDE 80
#define OFF_A  0
#define OFF_B  10240
#define STAGE_SZ 30720
#define NSTAGE 4
#define OFF_W2 (STAGE_SZ * NSTAGE)
#define OFF_B1 (OFF_W2 + 1024)
#define SMEM_FFN (OFF_B1 + 1024)
#define NIT (D_DIM / 32)

__global__ void __launch_bounds__(256, 1) k_ffn(const float* __restrict__ b1) {
    extern __shared__ char smem[];
    const uint32_t sbase = smem_u32(smem);
    const int tid = threadIdx.x;
    const int lane = tid & 31, wid = tid >> 5;
    const int wm = wid >> 2, wn = wid & 3;
    const int e = blockIdx.z;
    const int row0 = blockIdx.y * 128;
    const int col0 = blockIdx.x * 256;

    float* sW2 = (float*)(smem + OFF_W2);
    float* sB1 = (float*)(smem + OFF_B1);
    sW2[tid] = g_w2sum[e * H_DIM + col0 + tid];
    sB1[tid] = b1[(size_t)e * H_DIM + col0 + tid];

    const int alr = tid >> 1;
    const int akseg = tid & 1;
    const int srcTok = g_src[e * C_CAP + row0 + alr];
    const int aPred = (srcTok >= 0) ? 16 : 0;
    const __half* aPtr = g_xh + (size_t)(srcTok >= 0 ? srcTok : 0) * D_DIM + akseg * 16;
    const int aByte = alr * STRIDE + akseg * 32;
    const int br0 = tid >> 1,         bk0 = tid & 1;
    const int br1 = (tid + 256) >> 1, bk1 = tid & 1;
    const __half* bPtr0 = g_w1h + (size_t)(e * H_DIM + col0 + br0) * D_DIM + bk0 * 16;
    const __half* bPtr1 = g_w1h + (size_t)(e * H_DIM + col0 + br1) * D_DIM + bk1 * 16;
    const int bByte0 = br0 * STRIDE + bk0 * 32;
    const int bByte1 = br1 * STRIDE + bk1 * 32;

    float acc[4][8][4];
#pragma unroll
    for (int i = 0; i < 4; i++)
#pragma unroll
        for (int j = 0; j < 8; j++)
#pragma unroll
            for (int q = 0; q < 4; q++) acc[i][j][q] = 0.f;

    auto issue = [&](int it, int st) {
        const uint32_t sb = sbase + st * STAGE_SZ;
        const int co = it * 32;
        CP16Z(sb + OFF_A + aByte,      aPtr + co,     aPred);
        CP16Z(sb + OFF_A + aByte + 16, aPtr + co + 8, aPred);
        CP16(sb + OFF_B + bByte0,      bPtr0 + co);
        CP16(sb + OFF_B + bByte0 + 16, bPtr0 + co + 8);
        CP16(sb + OFF_B + bByte1,      bPtr1 + co);
        CP16(sb + OFF_B + bByte1 + 16, bPtr1 + co + 8);
    };

    issue(0, 0); CP_COMMIT();
    issue(1, 1); CP_COMMIT();
    issue(2, 2); CP_COMMIT();

    const uint32_t aFragOff = (wm * 64 + (lane & 15)) * STRIDE + ((lane >> 4) << 4);
    const uint32_t bFragOff = (wn * 64 + (lane & 15)) * STRIDE + ((lane >> 4) << 4);

    for (int it = 0; it < NIT; it++) {
        const int st = it & (NSTAGE - 1);
        CP_WAIT2();
        __syncthreads();
        if (it + 3 < NIT) issue(it + 3, (it + 3) & (NSTAGE - 1));
        CP_COMMIT();

        const uint32_t aB = sbase + st * STAGE_SZ + OFF_A + aFragOff;
        const uint32_t bB = sbase + st * STAGE_SZ + OFF_B + bFragOff;
#pragma unroll
        for (int kh = 0; kh < 2; kh++) {
            uint32_t a[4][4], b[8][2];
#pragma unroll
            for (int ma = 0; ma < 4; ma++)
                LDM4(a[ma], aB + ma * (16 * STRIDE) + kh * 32);
#pragma unroll
            for (int np = 0; np < 4; np++) {
                uint32_t tr[4];
                LDM4(tr, bB + np * (16 * STRIDE) + kh * 32);
                b[np * 2][0] = tr[0];     b[np * 2][1] = tr[2];
                b[np * 2 + 1][0] = tr[1]; b[np * 2 + 1][1] = tr[3];
            }
#pragma unroll
            for (int ma = 0; ma < 4; ma++)
#pragma unroll
                for (int na = 0; na < 8; na++)
                    MMA(acc[ma][na], a[ma], b[na]);
        }
    }

#pragma unroll
    for (int ma = 0; ma < 4; ma++) {
        float s0 = 0.f, s1 = 0.f;
#pragma unroll
        for (int na = 0; na < 8; na++) {
            int cb = wn * 64 + na * 8 + (lane & 3) * 2;
            float w0 = sW2[cb], w1v = sW2[cb + 1];
            float bb0 = sB1[cb], bb1 = sB1[cb + 1];
            s0 += fmaxf(acc[ma][na][0] + bb0, 0.f) * w0
                + fmaxf(acc[ma][na][1] + bb1, 0.f) * w1v;
            s1 += fmaxf(acc[ma][na][2] + bb0, 0.f) * w0
                + fmaxf(acc[ma][na][3] + bb1, 0.f) * w1v;
        }
        s0 += __shfl_xor_sync(0xffffffffu, s0, 1);
        s0 += __shfl_xor_sync(0xffffffffu, s0, 2);
        s1 += __shfl_xor_sync(0xffffffffu, s1, 1);
        s1 += __shfl_xor_sync(0xffffffffu, s1, 2);
        if ((lane & 3) == 0) {
            int r = row0 + wm * 64 + ma * 16 + (lane >> 2);
            atomicAdd(&g_rowsum[e * C_CAP + r], s0);
            atomicAdd(&g_rowsum[e * C_CAP + r + 8], s1);
        }
    }
}

// ================= K4: fused combine + log_softmax (1024 threads) =================
__global__ void __launch_bounds__(1024) k_out(float* __restrict__ out) {
    __shared__ float sy[S_SEQ];
    __shared__ float red[1024];
    const int b = blockIdx.x, tid = threadIdx.x;

    for (int s = tid; s < S_SEQ; s += 1024) {
        int t = b * S_SEQ + s;
        float y = 0.f;
        int p0 = g_p0[t];
        if (p0 >= 0) {
            int e = g_e0[t];
            y += g_g0[t] * (g_rowsum[e * C_CAP + p0] + g_b2sum[e]);
        }
        int p1 = g_p1[t];
        if (p1 >= 0) {
            int e = g_e1[t];
            y += g_g1[t] * (g_rowsum[e * C_CAP + p1] + g_b2sum[e]);
        }
        sy[s] = y;
    }
    __syncthreads();

    float m = fmaxf(sy[tid], sy[tid + 1024]);
    red[tid] = m; __syncthreads();
    for (int off = 512; off > 0; off >>= 1) {
        if (tid < off) red[tid] = fmaxf(red[tid], red[tid + off]);
        __syncthreads();
    }
    m = red[0]; __syncthreads();

    float sum = expf(sy[tid] - m) + expf(sy[tid + 1024] - m);
    red[tid] = sum; __syncthreads();
    for (int off = 512; off > 0; off >>= 1) {
        if (tid < off) red[tid] += red[tid + off];
        __syncthreads();
    }
    float lse = m + logf(red[0]);

    out[(size_t)b * S_SEQ + tid] = sy[tid] - lse;
    out[(size_t)b * S_SEQ + tid + 1024] = sy[tid + 1024] - lse;
}

// ---------------- launch ----------------
extern "C" void kernel_launch(void* const* d_in, const int* in_sizes, int n_in,
                              void* d_out, int out_size) {
    const float* x  = (const float*)d_in[0];
    const float* Wg = (const float*)d_in[1];
    const float* W1 = (const float*)d_in[2];
    const float* b1 = (const float*)d_in[3];
    const float* W2 = (const float*)d_in[4];
    const float* b2 = (const float*)d_in[5];
    float* out = (float*)d_out;

    cudaFuncSetAttribute(k_ffn, cudaFuncAttributeMaxDynamicSharedMemorySize, SMEM_FFN);

    k_prep<<<G_PREP, 256>>>(x, Wg, W1, W2, b2);
    k_scan<<<1, 1024>>>();
    k_ffn<<<dim3(H_DIM / 256, C_CAP / 128, E_EXP), 256, SMEM_FFN>>>(b1);
    k_out<<<B_BATCH, 1024>>>(out);
}

// round 11
// speedup vs baseline: 4.7858x; 1.0233x over previous
#include <cuda_runtime.h>
#include <cuda_fp16.h>
#include <math.h>
#include <stdint.h>

// Problem dims (fixed by setup_inputs)
#define T_TOK 8192
#define D_DIM 2048
#define E_EXP 8
#define H_DIM 2048
#define C_CAP 2048
#define B_BATCH 4
#define S_SEQ 2048

// ---------------- device scratch (allocation-free) ----------------
__device__ int   g_e0[T_TOK], g_e1[T_TOK];
__device__ float g_g0[T_TOK], g_g1[T_TOK];
__device__ int   g_p0[T_TOK], g_p1[T_TOK];
__device__ int   g_src[E_EXP * C_CAP];
__device__ float g_w2sum[E_EXP * H_DIM];
__device__ float g_b2sum[E_EXP];
__device__ float g_rowsum[E_EXP * C_CAP];
// fp16 copies: x (written by prep/gate), W1 transposed [e][h][d]
__device__ __align__(16) __half g_xh[(size_t)T_TOK * D_DIM];
__device__ __align__(16) __half g_w1h[(size_t)E_EXP * H_DIM * D_DIM];

// ---------------- helpers ----------------
__device__ __forceinline__ uint32_t smem_u32(const void* p) {
    uint32_t a;
    asm("{ .reg .u64 t; cvta.to.shared.u64 t, %1; cvt.u32.u64 %0, t; }" : "=r"(a) : "l"(p));
    return a;
}
#define LDM4(d, a) \
    asm volatile("ldmatrix.sync.aligned.m8n8.x4.shared.b16 {%0,%1,%2,%3}, [%4];" \
        : "=r"((d)[0]), "=r"((d)[1]), "=r"((d)[2]), "=r"((d)[3]) : "r"(a))
#define MMA(c, a, b) \
    asm volatile("mma.sync.aligned.m16n8k16.row.col.f32.f16.f16.f32 " \
        "{%0,%1,%2,%3},{%4,%5,%6,%7},{%8,%9},{%0,%1,%2,%3};" \
        : "+f"((c)[0]), "+f"((c)[1]), "+f"((c)[2]), "+f"((c)[3]) \
        : "r"((a)[0]), "r"((a)[1]), "r"((a)[2]), "r"((a)[3]), "r"((b)[0]), "r"((b)[1]))
#define CP16(dst, src) \
    asm volatile("cp.async.ca.shared.global [%0], [%1], 16;" :: "r"(dst), "l"(src) : "memory")
#define CP16Z(dst, src, n) \
    asm volatile("cp.async.ca.shared.global [%0], [%1], 16, %2;" :: "r"(dst), "l"(src), "r"(n) : "memory")
#define CP_COMMIT() asm volatile("cp.async.commit_group;" ::: "memory")
#define CP_WAIT2()  asm volatile("cp.async.wait_group 2;" ::: "memory")

// ================= K1: fused prep =================
// Interleaved roles, period 6: [4 w1t | 1 gate(4 tokens, 2 warps each) | 1 w2sum(8 rows)] x 2048,
// then 64 init blocks + 1 b2sum block.
#define GB_PERIOD 6
#define G_MAIN (2048 * GB_PERIOD)      // 12288
#define G_INIT 64
#define G_PREP (G_MAIN + G_INIT + 1)

__global__ void __launch_bounds__(256) k_prep(const float* __restrict__ x,
                                              const float* __restrict__ Wg,
                                              const float* __restrict__ W1,
                                              const float* __restrict__ W2,
                                              const float* __restrict__ b2) {
    __shared__ float tl[64][65];
    __shared__ float sm_g[4][2][8];
    const int bid = blockIdx.x, tid = threadIdx.x;
    const int lane = tid & 31, wrp = tid >> 5;

    if (bid < G_MAIN) {
        const int p = bid / GB_PERIOD, r = bid % GB_PERIOD;
        if (r < 4) {
            // ---- w1t: transpose W1 -> [e][h][d] fp16, 64x64 tile, vectorized ----
            const int w = p * 4 + r;               // 0..8191
            const int e = w >> 10;                 // 1024 tiles per expert
            const int rem = w & 1023;
            const int h0 = (rem >> 5) * 64, d0 = (rem & 31) * 64;
            // load: 16 threads x float4 cover one 64-wide d-row; 16 rows in flight
            const int hx = (tid & 15) * 4;
            const int dB = tid >> 4;               // 0..15
#pragma unroll
            for (int i = 0; i < 4; i++) {
                const int dl = dB + i * 16;
                float4 v = *(const float4*)&W1[((size_t)e * D_DIM + d0 + dl) * H_DIM + h0 + hx];
                tl[dl][hx] = v.x; tl[dl][hx + 1] = v.y;
                tl[dl][hx + 2] = v.z; tl[dl][hx + 3] = v.w;
            }
            __syncthreads();
            // store: 32 threads x half2 cover one 64-wide h-row; 8 rows in flight
            const int dp = tid & 31;
            const int hB = tid >> 5;               // 0..7
#pragma unroll
            for (int i = 0; i < 8; i++) {
                const int hl = hB + i * 8;
                __half2 hv = __floats2half2_rn(tl[2 * dp][hl], tl[2 * dp + 1][hl]);
                *(__half2*)&g_w1h[((size_t)e * H_DIM + h0 + hl) * D_DIM + d0 + 2 * dp] = hv;
            }
        } else if (r == 4) {
            // ---- gate: 4 tokens, 2 warps per token (split-K), exact fp32 routing + x->fp16 ----
            const int tok = p * 4 + (wrp >> 1);
            const int half = wrp & 1;
            const float* xr = x + (size_t)tok * D_DIM;
            __half* xhw = g_xh + (size_t)tok * D_DIM;
            float acc[8];
#pragma unroll
            for (int e = 0; e < 8; e++) acc[e] = 0.f;
#pragma unroll
            for (int i = 0; i < 8; i++) {
                const int k = (half * 256 + i * 32 + lane) * 4;
                float4 xv = *(const float4*)(xr + k);
                *(__half2*)(xhw + k)     = __floats2half2_rn(xv.x, xv.y);
                *(__half2*)(xhw + k + 2) = __floats2half2_rn(xv.z, xv.w);
                const float xs[4] = {xv.x, xv.y, xv.z, xv.w};
#pragma unroll
                for (int j = 0; j < 4; j++) {
                    const float* wr = Wg + (size_t)(k + j) * 8;
                    float4 w0 = *(const float4*)(wr);
                    float4 w1v = *(const float4*)(wr + 4);
                    acc[0] = fmaf(xs[j], w0.x, acc[0]);
                    acc[1] = fmaf(xs[j], w0.y, acc[1]);
                    acc[2] = fmaf(xs[j], w0.z, acc[2]);
                    acc[3] = fmaf(xs[j], w0.w, acc[3]);
                    acc[4] = fmaf(xs[j], w1v.x, acc[4]);
                    acc[5] = fmaf(xs[j], w1v.y, acc[5]);
                    acc[6] = fmaf(xs[j], w1v.z, acc[6]);
                    acc[7] = fmaf(xs[j], w1v.w, acc[7]);
                }
            }
#pragma unroll
            for (int e = 0; e < 8; e++) {
#pragma unroll
                for (int off = 16; off > 0; off >>= 1)
                    acc[e] += __shfl_xor_sync(0xffffffffu, acc[e], off);
            }
            if (lane == 0) {
#pragma unroll
                for (int e = 0; e < 8; e++) sm_g[wrp >> 1][half][e] = acc[e];
            }
            __syncthreads();
            if (wrp < 4 && lane == 0) {
                const int t2 = p * 4 + wrp;
                float l0 = -INFINITY, l1 = -INFINITY;
                int i0 = 0, i1 = 0;
#pragma unroll
                for (int e = 0; e < 8; e++) {
                    float v = sm_g[wrp][0][e] + sm_g[wrp][1][e];
                    if (v > l0) { l1 = l0; i1 = i0; l0 = v; i0 = e; }
                    else if (v > l1) { l1 = v; i1 = e; }
                }
                float g0 = 1.f / (1.f + __expf(l1 - l0));
                g_e0[t2] = i0; g_e1[t2] = i1;
                g_g0[t2] = g0; g_g1[t2] = 1.f - g0;
            }
        } else {
            // ---- w2sum: one warp per (e,h) row, 8 rows per block ----
            const int gw = p * 8 + wrp;            // < 16384
            const float* rr = W2 + (size_t)gw * D_DIM;
            float s = 0.f;
            for (int k = lane * 4; k < D_DIM; k += 128) {
                float4 vv = *(const float4*)(rr + k);
                s += (vv.x + vv.y) + (vv.z + vv.w);
            }
#pragma unroll
            for (int off = 16; off > 0; off >>= 1) s += __shfl_xor_sync(0xffffffffu, s, off);
            if (lane == 0) g_w2sum[gw] = s;
        }
    } else if (bid < G_MAIN + G_INIT) {
        int i = (bid - G_MAIN) * 256 + tid;
        g_src[i] = -1;
        g_rowsum[i] = 0.f;
    } else {
        if (wrp < 8) {
            float s = 0.f;
            for (int k = lane; k < D_DIM; k += 32) s += b2[(size_t)wrp * D_DIM + k];
#pragma unroll
            for (int off = 16; off > 0; off >>= 1) s += __shfl_xor_sync(0xffffffffu, s, off);
            if (lane == 0) g_b2sum[wrp] = s;
        }
    }
}

// ================= K2: dispatch scan (1024 threads, both choices in one pass) =================
__global__ void __launch_bounds__(1024) k_scan() {
    __shared__ int wT0[32][8], wT1[32][8];
    __shared__ int wOff0[32][8], wOff1[32][8];
    __shared__ int shTot[8];
    const int tid = threadIdx.x, lane = tid & 31, w = tid >> 5;
    const int base = tid * 8;

    int4 a0 = *(const int4*)&g_e0[base];
    int4 a1 = *(const int4*)&g_e0[base + 4];
    int4 c0 = *(const int4*)&g_e1[base];
    int4 c1 = *(const int4*)&g_e1[base + 4];
    const int e0s[8] = {a0.x, a0.y, a0.z, a0.w, a1.x, a1.y, a1.z, a1.w};
    const int e1s[8] = {c0.x, c0.y, c0.z, c0.w, c1.x, c1.y, c1.z, c1.w};

    int cnt0[8], cnt1[8];
#pragma unroll
    for (int e = 0; e < 8; e++) { cnt0[e] = 0; cnt1[e] = 0; }
#pragma unroll
    for (int i = 0; i < 8; i++) { cnt0[e0s[i]]++; cnt1[e1s[i]]++; }

    int inc0[8], inc1[8];
#pragma unroll
    for (int e = 0; e < 8; e++) { inc0[e] = cnt0[e]; inc1[e] = cnt1[e]; }
#pragma unroll
    for (int off = 1; off < 32; off <<= 1) {
#pragma unroll
        for (int e = 0; e < 8; e++) {
            int v0 = __shfl_up_sync(0xffffffffu, inc0[e], off);
            int v1 = __shfl_up_sync(0xffffffffu, inc1[e], off);
            if (lane >= off) { inc0[e] += v0; inc1[e] += v1; }
        }
    }
    if (lane == 31) {
#pragma unroll
        for (int e = 0; e < 8; e++) { wT0[w][e] = inc0[e]; wT1[w][e] = inc1[e]; }
    }
    __syncthreads();
    if (w == 0) {
        int t0[8], t1[8], i0[8], i1[8];
#pragma unroll
        for (int e = 0; e < 8; e++) {
            t0[e] = wT0[lane][e]; t1[e] = wT1[lane][e];
            i0[e] = t0[e]; i1[e] = t1[e];
        }
#pragma unroll
        for (int off = 1; off < 32; off <<= 1) {
#pragma unroll
            for (int e = 0; e < 8; e++) {
                int v0 = __shfl_up_sync(0xffffffffu, i0[e], off);
                int v1 = __shfl_up_sync(0xffffffffu, i1[e], off);
                if (lane >= off) { i0[e] += v0; i1[e] += v1; }
            }
        }
#pragma unroll
        for (int e = 0; e < 8; e++) {
            wOff0[lane][e] = i0[e] - t0[e];
            wOff1[lane][e] = i1[e] - t1[e];
        }
        if (lane == 31) {
#pragma unroll
            for (int e = 0; e < 8; e++) shTot[e] = i0[e];
        }
    }
    __syncthreads();

    int run0[8], run1[8];
#pragma unroll
    for (int e = 0; e < 8; e++) {
        run0[e] = wOff0[w][e] + inc0[e] - cnt0[e];
        run1[e] = shTot[e] + wOff1[w][e] + inc1[e] - cnt1[e];
    }
#pragma unroll
    for (int i = 0; i < 8; i++) {
        int tok = base + i;
        int e = e0s[i];
        int pos = run0[e]++;
        if (pos < C_CAP) { g_p0[tok] = pos; g_src[e * C_CAP + pos] = tok; }
        else             { g_p0[tok] = -1; }
    }
#pragma unroll
    for (int i = 0; i < 8; i++) {
        int tok = base + i;
        int e = e1s[i];
        int pos = run1[e]++;
        if (pos < C_CAP) { g_p1[tok] = pos; g_src[e * C_CAP + pos] = tok; }
        else             { g_p1[tok] = -1; }
    }
}

// ================= K3: HMMA fused expert GEMM + relu*w2sum epilogue (unchanged) =================
#define STRIDE 80
#define OFF_A  0
#define OFF_B  10240
#define STAGE_SZ 30720
#define NSTAGE 4
#define OFF_W2 (STAGE_SZ * NSTAGE)
#define OFF_B1 (OFF_W2 + 1024)
#define SMEM_FFN (OFF_B1 + 1024)
#define NIT (D_DIM / 32)

__global__ void __launch_bounds__(256, 1) k_ffn(const float* __restrict__ b1) {
    extern __shared__ char smem[];
    const uint32_t sbase = smem_u32(smem);
    const int tid = threadIdx.x;
    const int lane = tid & 31, wid = tid >> 5;
    const int wm = wid >> 2, wn = wid & 3;
    const int e = blockIdx.z;
    const int row0 = blockIdx.y * 128;
    const int col0 = blockIdx.x * 256;

    float* sW2 = (float*)(smem + OFF_W2);
    float* sB1 = (float*)(smem + OFF_B1);
    sW2[tid] = g_w2sum[e * H_DIM + col0 + tid];
    sB1[tid] = b1[(size_t)e * H_DIM + col0 + tid];

    const int alr = tid >> 1;
    const int akseg = tid & 1;
    const int srcTok = g_src[e * C_CAP + row0 + alr];
    const int aPred = (srcTok >= 0) ? 16 : 0;
    const __half* aPtr = g_xh + (size_t)(srcTok >= 0 ? srcTok : 0) * D_DIM + akseg * 16;
    const int aByte = alr * STRIDE + akseg * 32;
    const int br0 = tid >> 1,         bk0 = tid & 1;
    const int br1 = (tid + 256) >> 1, bk1 = tid & 1;
    const __half* bPtr0 = g_w1h + (size_t)(e * H_DIM + col0 + br0) * D_DIM + bk0 * 16;
    const __half* bPtr1 = g_w1h + (size_t)(e * H_DIM + col0 + br1) * D_DIM + bk1 * 16;
    const int bByte0 = br0 * STRIDE + bk0 * 32;
    const int bByte1 = br1 * STRIDE + bk1 * 32;

    float acc[4][8][4];
#pragma unroll
    for (int i = 0; i < 4; i++)
#pragma unroll
        for (int j = 0; j < 8; j++)
#pragma unroll
            for (int q = 0; q < 4; q++) acc[i][j][q] = 0.f;

    auto issue = [&](int it, int st) {
        const uint32_t sb = sbase + st * STAGE_SZ;
        const int co = it * 32;
        CP16Z(sb + OFF_A + aByte,      aPtr + co,     aPred);
        CP16Z(sb + OFF_A + aByte + 16, aPtr + co + 8, aPred);
        CP16(sb + OFF_B + bByte0,      bPtr0 + co);
        CP16(sb + OFF_B + bByte0 + 16, bPtr0 + co + 8);
        CP16(sb + OFF_B + bByte1,      bPtr1 + co);
        CP16(sb + OFF_B + bByte1 + 16, bPtr1 + co + 8);
    };

    issue(0, 0); CP_COMMIT();
    issue(1, 1); CP_COMMIT();
    issue(2, 2); CP_COMMIT();

    const uint32_t aFragOff = (wm * 64 + (lane & 15)) * STRIDE + ((lane >> 4) << 4);
    const uint32_t bFragOff = (wn * 64 + (lane & 15)) * STRIDE + ((lane >> 4) << 4);

    for (int it = 0; it < NIT; it++) {
        const int st = it & (NSTAGE - 1);
        CP_WAIT2();
        __syncthreads();
        if (it + 3 < NIT) issue(it + 3, (it + 3) & (NSTAGE - 1));
        CP_COMMIT();

        const uint32_t aB = sbase + st * STAGE_SZ + OFF_A + aFragOff;
        const uint32_t bB = sbase + st * STAGE_SZ + OFF_B + bFragOff;
#pragma unroll
        for (int kh = 0; kh < 2; kh++) {
            uint32_t a[4][4], b[8][2];
#pragma unroll
            for (int ma = 0; ma < 4; ma++)
                LDM4(a[ma], aB + ma * (16 * STRIDE) + kh * 32);
#pragma unroll
            for (int np = 0; np < 4; np++) {
                uint32_t tr[4];
                LDM4(tr, bB + np * (16 * STRIDE) + kh * 32);
                b[np * 2][0] = tr[0];     b[np * 2][1] = tr[2];
                b[np * 2 + 1][0] = tr[1]; b[np * 2 + 1][1] = tr[3];
            }
#pragma unroll
            for (int ma = 0; ma < 4; ma++)
#pragma unroll
                for (int na = 0; na < 8; na++)
                    MMA(acc[ma][na], a[ma], b[na]);
        }
    }

#pragma unroll
    for (int ma = 0; ma < 4; ma++) {
        float s0 = 0.f, s1 = 0.f;
#pragma unroll
        for (int na = 0; na < 8; na++) {
            int cb = wn * 64 + na * 8 + (lane & 3) * 2;
            float w0 = sW2[cb], w1v = sW2[cb + 1];
            float bb0 = sB1[cb], bb1 = sB1[cb + 1];
            s0 += fmaxf(acc[ma][na][0] + bb0, 0.f) * w0
                + fmaxf(acc[ma][na][1] + bb1, 0.f) * w1v;
            s1 += fmaxf(acc[ma][na][2] + bb0, 0.f) * w0
                + fmaxf(acc[ma][na][3] + bb1, 0.f) * w1v;
        }
        s0 += __shfl_xor_sync(0xffffffffu, s0, 1);
        s0 += __shfl_xor_sync(0xffffffffu, s0, 2);
        s1 += __shfl_xor_sync(0xffffffffu, s1, 1);
        s1 += __shfl_xor_sync(0xffffffffu, s1, 2);
        if ((lane & 3) == 0) {
            int r = row0 + wm * 64 + ma * 16 + (lane >> 2);
            atomicAdd(&g_rowsum[e * C_CAP + r], s0);
            atomicAdd(&g_rowsum[e * C_CAP + r + 8], s1);
        }
    }
}

// ================= K4: fused combine + log_softmax (1024 threads) =================
__global__ void __launch_bounds__(1024) k_out(float* __restrict__ out) {
    __shared__ float sy[S_SEQ];
    __shared__ float red[1024];
    const int b = blockIdx.x, tid = threadIdx.x;

    for (int s = tid; s < S_SEQ; s += 1024) {
        int t = b * S_SEQ + s;
        float y = 0.f;
        int p0 = g_p0[t];
        if (p0 >= 0) {
            int e = g_e0[t];
            y += g_g0[t] * (g_rowsum[e * C_CAP + p0] + g_b2sum[e]);
        }
        int p1 = g_p1[t];
        if (p1 >= 0) {
            int e = g_e1[t];
            y += g_g1[t] * (g_rowsum[e * C_CAP + p1] + g_b2sum[e]);
        }
        sy[s] = y;
    }
    __syncthreads();

    float m = fmaxf(sy[tid], sy[tid + 1024]);
    red[tid] = m; __syncthreads();
    for (int off = 512; off > 0; off >>= 1) {
        if (tid < off) red[tid] = fmaxf(red[tid], red[tid + off]);
        __syncthreads();
    }
    m = red[0]; __syncthreads();

    float sum = expf(sy[tid] - m) + expf(sy[tid + 1024] - m);
    red[tid] = sum; __syncthreads();
    for (int off = 512; off > 0; off >>= 1) {
        if (tid < off) red[tid] += red[tid + off];
        __syncthreads();
    }
    float lse = m + logf(red[0]);

    out[(size_t)b * S_SEQ + tid] = sy[tid] - lse;
    out[(size_t)b * S_SEQ + tid + 1024] = sy[tid + 1024] - lse;
}

// ---------------- launch ----------------
extern "C" void kernel_launch(void* const* d_in, const int* in_sizes, int n_in,
                              void* d_out, int out_size) {
    const float* x  = (const float*)d_in[0];
    const float* Wg = (const float*)d_in[1];
    const float* W1 = (const float*)d_in[2];
    const float* b1 = (const float*)d_in[3];
    const float* W2 = (const float*)d_in[4];
    const float* b2 = (const float*)d_in[5];
    float* out = (float*)d_out;

    cudaFuncSetAttribute(k_ffn, cudaFuncAttributeMaxDynamicSharedMemorySize, SMEM_FFN);

    k_prep<<<G_PREP, 256>>>(x, Wg, W1, W2, b2);
    k_scan<<<1, 1024>>>();
    k_ffn<<<dim3(H_DIM / 256, C_CAP / 128, E_EXP), 256, SMEM_FFN>>>(b1);
    k_out<<<B_BATCH, 1024>>>(out);
}